// round 2
// baseline (speedup 1.0000x reference)
#include <cuda_runtime.h>
#include <math.h>

#define HNUM   12
#define DMODEL 768
#define BATCH  2
#define SEQ    2048
#define DK     64
#define MTOT   (BATCH * SEQ)          // 4096

// ---------------------------------------------------------------------------
// Scratch (allocation-free): Q,K,V in [B,H,S,DK]; attention out in [B,S,H*DK]
// ---------------------------------------------------------------------------
__device__ float g_q[BATCH * HNUM * SEQ * DK];
__device__ float g_k[BATCH * HNUM * SEQ * DK];
__device__ float g_v[BATCH * HNUM * SEQ * DK];
__device__ float g_ao[BATCH * SEQ * DMODEL];

// ---------------------------------------------------------------------------
// Generic NT GEMM: out = (A[M,768] @ W[N,768]^T + bias) * scale
// layout 0: out[M,N] row-major.  layout 1: out as [B,H,S,DK] (col = h*64+d).
// Block tile 64x64, 256 threads, 4x4 per thread, K-tile 16.
// ---------------------------------------------------------------------------
__global__ void __launch_bounds__(256) gemm_nt_kernel(
    const float* __restrict__ A, const float* __restrict__ W,
    const float* __restrict__ bias, float* __restrict__ out,
    float scale, int layout)
{
    __shared__ __align__(16) float As[16][68];
    __shared__ __align__(16) float Ws[16][68];

    const int bm = blockIdx.y * 64;
    const int bn = blockIdx.x * 64;
    const int t  = threadIdx.x;
    const int ty = t >> 4;          // 0..15
    const int tx = t & 15;          // 0..15
    const int lm = t >> 2;          // 0..63 (row within tile for loads)
    const int lk = (t & 3) << 2;    // 0,4,8,12 (k offset for loads)

    const float* Ap = A + (size_t)(bm + lm) * DMODEL + lk;
    const float* Wp = W + (size_t)(bn + lm) * DMODEL + lk;

    float acc[4][4];
#pragma unroll
    for (int i = 0; i < 4; i++)
#pragma unroll
        for (int j = 0; j < 4; j++) acc[i][j] = 0.0f;

#pragma unroll 4
    for (int k0 = 0; k0 < DMODEL; k0 += 16) {
        float4 av = *(const float4*)(Ap + k0);
        float4 wv = *(const float4*)(Wp + k0);
        As[lk + 0][lm] = av.x; As[lk + 1][lm] = av.y;
        As[lk + 2][lm] = av.z; As[lk + 3][lm] = av.w;
        Ws[lk + 0][lm] = wv.x; Ws[lk + 1][lm] = wv.y;
        Ws[lk + 2][lm] = wv.z; Ws[lk + 3][lm] = wv.w;
        __syncthreads();

#pragma unroll
        for (int k = 0; k < 16; k++) {
            float4 a4 = *(const float4*)(&As[k][ty << 2]);
            float4 b4 = *(const float4*)(&Ws[k][tx << 2]);
            float aa[4] = {a4.x, a4.y, a4.z, a4.w};
            float bb[4] = {b4.x, b4.y, b4.z, b4.w};
#pragma unroll
            for (int i = 0; i < 4; i++)
#pragma unroll
                for (int j = 0; j < 4; j++)
                    acc[i][j] = fmaf(aa[i], bb[j], acc[i][j]);
        }
        __syncthreads();
    }

#pragma unroll
    for (int i = 0; i < 4; i++) {
        const int row = bm + (ty << 2) + i;
        const int b   = row / SEQ;
        const int s   = row % SEQ;
#pragma unroll
        for (int j = 0; j < 4; j++) {
            const int col = bn + (tx << 2) + j;
            const float v = (acc[i][j] + bias[col]) * scale;
            if (layout == 0) {
                out[(size_t)row * DMODEL + col] = v;
            } else {
                const int h = col >> 6;
                const int d = col & 63;
                out[(((size_t)b * HNUM + h) * SEQ + s) * DK + d] = v;
            }
        }
    }
}

// ---------------------------------------------------------------------------
// Fused flash-style attention: one block per (b*H+h, 64-query tile).
// Q pre-scaled by 1/8. Online softmax, P staged in smem for the PV GEMM.
// Output written as [B, S, H*DK] for the final projection.
// ---------------------------------------------------------------------------
#define ASTR 68   // smem row stride (floats), 272B => 16B-aligned rows

__global__ void __launch_bounds__(256) attn_kernel(
    const float* __restrict__ Q, const float* __restrict__ K,
    const float* __restrict__ V, const int* __restrict__ mask,
    float* __restrict__ out)
{
    extern __shared__ __align__(16) float sm[];
    float* Qs  = sm;                     // 64 x ASTR
    float* KVs = sm + 64 * ASTR;         // 64 x ASTR (K then V)
    float* Ps  = sm + 2 * 64 * ASTR;     // 64 x ASTR
    __shared__ int msk[64];

    const int t  = threadIdx.x;
    const int ty = t >> 4;
    const int tx = t & 15;
    const int bh = blockIdx.y;
    const int b  = bh / HNUM;
    const int h  = bh % HNUM;
    const int q0 = blockIdx.x * 64;

    const float* Qbase = Q + ((size_t)bh * SEQ + q0) * DK;
    const float* Kbase = K + (size_t)bh * SEQ * DK;
    const float* Vbase = V + (size_t)bh * SEQ * DK;

    // Load Q tile (64x64) -> Qs
    for (int idx = t; idx < 64 * 16; idx += 256) {
        const int r = idx >> 4;
        const int c = (idx & 15) << 2;
        *(float4*)(&Qs[r * ASTR + c]) = *(const float4*)(Qbase + r * DK + c);
    }

    float o[4][4];
    float mreg[4], lreg[4];
#pragma unroll
    for (int i = 0; i < 4; i++) {
        mreg[i] = -1e30f;
        lreg[i] = 0.0f;
#pragma unroll
        for (int j = 0; j < 4; j++) o[i][j] = 0.0f;
    }

    for (int j0 = 0; j0 < SEQ; j0 += 64) {
        // Load K tile
        for (int idx = t; idx < 64 * 16; idx += 256) {
            const int r = idx >> 4;
            const int c = (idx & 15) << 2;
            *(float4*)(&KVs[r * ASTR + c]) =
                *(const float4*)(Kbase + (size_t)(j0 + r) * DK + c);
        }
        if (t < 64) msk[t] = mask[b * SEQ + j0 + t];
        __syncthreads();

        // S = Qs @ Ks^T  (thread owns rows ty*4.., cols tx*4..)
        float s[4][4];
#pragma unroll
        for (int i = 0; i < 4; i++)
#pragma unroll
            for (int j = 0; j < 4; j++) s[i][j] = 0.0f;

        for (int d = 0; d < DK; d += 4) {
            float4 qa[4], kb[4];
#pragma unroll
            for (int i = 0; i < 4; i++)
                qa[i] = *(const float4*)(&Qs[(ty * 4 + i) * ASTR + d]);
#pragma unroll
            for (int j = 0; j < 4; j++)
                kb[j] = *(const float4*)(&KVs[(tx * 4 + j) * ASTR + d]);
#pragma unroll
            for (int i = 0; i < 4; i++)
#pragma unroll
                for (int j = 0; j < 4; j++) {
                    s[i][j] = fmaf(qa[i].x, kb[j].x, s[i][j]);
                    s[i][j] = fmaf(qa[i].y, kb[j].y, s[i][j]);
                    s[i][j] = fmaf(qa[i].z, kb[j].z, s[i][j]);
                    s[i][j] = fmaf(qa[i].w, kb[j].w, s[i][j]);
                }
        }

        // Padding mask (replace with -1e9 like the reference)
#pragma unroll
        for (int j = 0; j < 4; j++) {
            if (msk[tx * 4 + j] == 0) {
#pragma unroll
                for (int i = 0; i < 4; i++) s[i][j] = -1e9f;
            }
        }

        // Online softmax update (row groups are 16-lane shuffle segments)
#pragma unroll
        for (int i = 0; i < 4; i++) {
            float tm = fmaxf(fmaxf(s[i][0], s[i][1]), fmaxf(s[i][2], s[i][3]));
#pragma unroll
            for (int off = 8; off >= 1; off >>= 1)
                tm = fmaxf(tm, __shfl_xor_sync(0xffffffffu, tm, off, 16));
            const float mn    = fmaxf(mreg[i], tm);
            const float alpha = __expf(mreg[i] - mn);
            mreg[i] = mn;
            float rs = 0.0f;
#pragma unroll
            for (int j = 0; j < 4; j++) {
                const float p = __expf(s[i][j] - mn);
                s[i][j] = p;
                rs += p;
            }
#pragma unroll
            for (int off = 8; off >= 1; off >>= 1)
                rs += __shfl_xor_sync(0xffffffffu, rs, off, 16);
            lreg[i] = lreg[i] * alpha + rs;
#pragma unroll
            for (int j = 0; j < 4; j++) o[i][j] *= alpha;
        }

        // Stage P
#pragma unroll
        for (int i = 0; i < 4; i++) {
            float4 p4 = make_float4(s[i][0], s[i][1], s[i][2], s[i][3]);
            *(float4*)(&Ps[(ty * 4 + i) * ASTR + tx * 4]) = p4;
        }
        __syncthreads();

        // Load V tile over K buffer
        for (int idx = t; idx < 64 * 16; idx += 256) {
            const int r = idx >> 4;
            const int c = (idx & 15) << 2;
            *(float4*)(&KVs[r * ASTR + c]) =
                *(const float4*)(Vbase + (size_t)(j0 + r) * DK + c);
        }
        __syncthreads();

        // O += P @ V   (thread owns rows ty*4.., dims tx*4..)
        for (int kk = 0; kk < 64; kk += 4) {
            float4 pv[4], vv[4];
#pragma unroll
            for (int i = 0; i < 4; i++)
                pv[i] = *(const float4*)(&Ps[(ty * 4 + i) * ASTR + kk]);
#pragma unroll
            for (int u = 0; u < 4; u++)
                vv[u] = *(const float4*)(&KVs[(kk + u) * ASTR + tx * 4]);
#pragma unroll
            for (int i = 0; i < 4; i++) {
                const float pc[4] = {pv[i].x, pv[i].y, pv[i].z, pv[i].w};
#pragma unroll
                for (int u = 0; u < 4; u++) {
                    o[i][0] = fmaf(pc[u], vv[u].x, o[i][0]);
                    o[i][1] = fmaf(pc[u], vv[u].y, o[i][1]);
                    o[i][2] = fmaf(pc[u], vv[u].z, o[i][2]);
                    o[i][3] = fmaf(pc[u], vv[u].w, o[i][3]);
                }
            }
        }
        __syncthreads();   // protect KVs/Ps before next tile's loads
    }

    // Epilogue: normalize and write [B, S, H*DK]
#pragma unroll
    for (int i = 0; i < 4; i++) {
        const float inv = 1.0f / lreg[i];
        const int srow  = q0 + ty * 4 + i;
        float* orow = out + (((size_t)b * SEQ + srow) * HNUM + h) * DK + tx * 4;
        float4 o4 = make_float4(o[i][0] * inv, o[i][1] * inv,
                                o[i][2] * inv, o[i][3] * inv);
        *(float4*)orow = o4;
    }
}

// ---------------------------------------------------------------------------
// Launch
// ---------------------------------------------------------------------------
extern "C" void kernel_launch(void* const* d_in, const int* in_sizes, int n_in,
                              void* d_out, int out_size)
{
    const float* query = (const float*)d_in[0];
    const float* key   = (const float*)d_in[1];
    const float* value = (const float*)d_in[2];
    const int*   mask  = (const int*)  d_in[3];
    const float* Wq    = (const float*)d_in[4];
    const float* bq    = (const float*)d_in[5];
    const float* Wk    = (const float*)d_in[6];
    const float* bk    = (const float*)d_in[7];
    const float* Wv    = (const float*)d_in[8];
    const float* bv    = (const float*)d_in[9];
    const float* Wo    = (const float*)d_in[10];
    const float* bo    = (const float*)d_in[11];

    float *qb, *kb, *vb, *ab;
    cudaGetSymbolAddress((void**)&qb, g_q);
    cudaGetSymbolAddress((void**)&kb, g_k);
    cudaGetSymbolAddress((void**)&vb, g_v);
    cudaGetSymbolAddress((void**)&ab, g_ao);

    const int attn_smem = 3 * 64 * ASTR * (int)sizeof(float);  // 52224 B
    cudaFuncSetAttribute(attn_kernel,
                         cudaFuncAttributeMaxDynamicSharedMemorySize, attn_smem);

    dim3 ggrid(DMODEL / 64, MTOT / 64);   // (12, 64)

    gemm_nt_kernel<<<ggrid, 256>>>(query, Wq, bq, qb, 0.125f, 1);
    gemm_nt_kernel<<<ggrid, 256>>>(key,   Wk, bk, kb, 1.0f,   1);
    gemm_nt_kernel<<<ggrid, 256>>>(value, Wv, bv, vb, 1.0f,   1);

    attn_kernel<<<dim3(SEQ / 64, BATCH * HNUM), 256, attn_smem>>>(
        qb, kb, vb, mask, ab);

    gemm_nt_kernel<<<ggrid, 256>>>(ab, Wo, bo, (float*)d_out, 1.0f, 0);
}

// round 4
// speedup vs baseline: 1.1832x; 1.1832x over previous
#include <cuda_runtime.h>
#include <cuda_bf16.h>
#include <cstdint>
#include <math.h>

#define HNUM   12
#define DMODEL 768
#define BATCH  2
#define SEQ    2048
#define DK     64
#define MTOT   (BATCH * SEQ)          // 4096

// ---------------------------------------------------------------------------
// Scratch (allocation-free)
// ---------------------------------------------------------------------------
__device__ float g_q[BATCH * HNUM * SEQ * DK];
__device__ float g_k[BATCH * HNUM * SEQ * DK];
__device__ float g_v[BATCH * HNUM * SEQ * DK];
__device__ float g_ao[BATCH * SEQ * DMODEL];

// bf16 hi/lo splits
__device__ __nv_bfloat16 g_ah[3 * MTOT * DMODEL];
__device__ __nv_bfloat16 g_al[3 * MTOT * DMODEL];
__device__ __nv_bfloat16 g_wh[4 * DMODEL * DMODEL];
__device__ __nv_bfloat16 g_wl[4 * DMODEL * DMODEL];
__device__ __nv_bfloat16 g_oh[MTOT * DMODEL];
__device__ __nv_bfloat16 g_ol[MTOT * DMODEL];

// ---------------------------------------------------------------------------
// Warp-MMA helpers (sm_80+; works on plain sm_100 target)
// ---------------------------------------------------------------------------
__device__ __forceinline__ uint32_t smem_to_u32(const void* p) {
    uint32_t a;
    asm("{ .reg .u64 t; cvta.to.shared.u64 t, %1; cvt.u32.u64 %0, t; }"
        : "=r"(a) : "l"(p));
    return a;
}

__device__ __forceinline__ void ldsm_x4(uint32_t& r0, uint32_t& r1,
                                        uint32_t& r2, uint32_t& r3, uint32_t addr) {
    asm volatile("ldmatrix.sync.aligned.m8n8.x4.shared.b16 {%0,%1,%2,%3}, [%4];"
                 : "=r"(r0), "=r"(r1), "=r"(r2), "=r"(r3) : "r"(addr));
}

__device__ __forceinline__ void mma_bf16(float* c, const uint32_t* a,
                                         uint32_t b0, uint32_t b1) {
    asm volatile("mma.sync.aligned.m16n8k16.row.col.f32.bf16.bf16.f32 "
                 "{%0,%1,%2,%3}, {%4,%5,%6,%7}, {%8,%9}, {%0,%1,%2,%3};"
                 : "+f"(c[0]), "+f"(c[1]), "+f"(c[2]), "+f"(c[3])
                 : "r"(a[0]), "r"(a[1]), "r"(a[2]), "r"(a[3]), "r"(b0), "r"(b1));
}

// ---------------------------------------------------------------------------
// fp32 -> bf16 hi/lo split (elementwise, vectorized)
// ---------------------------------------------------------------------------
__global__ void __launch_bounds__(256) cvt_split_kernel(
    const float* __restrict__ x, __nv_bfloat16* __restrict__ hi,
    __nv_bfloat16* __restrict__ lo, int n4)
{
    int i = blockIdx.x * 256 + threadIdx.x;
    if (i >= n4) return;
    float4 v = ((const float4*)x)[i];
    __nv_bfloat16 h0 = __float2bfloat16(v.x), h1 = __float2bfloat16(v.y);
    __nv_bfloat16 h2 = __float2bfloat16(v.z), h3 = __float2bfloat16(v.w);
    __nv_bfloat16 l0 = __float2bfloat16(v.x - __bfloat162float(h0));
    __nv_bfloat16 l1 = __float2bfloat16(v.y - __bfloat162float(h1));
    __nv_bfloat16 l2 = __float2bfloat16(v.z - __bfloat162float(h2));
    __nv_bfloat16 l3 = __float2bfloat16(v.w - __bfloat162float(h3));
    ((__nv_bfloat162*)hi)[2 * i]     = __nv_bfloat162(h0, h1);
    ((__nv_bfloat162*)hi)[2 * i + 1] = __nv_bfloat162(h2, h3);
    ((__nv_bfloat162*)lo)[2 * i]     = __nv_bfloat162(l0, l1);
    ((__nv_bfloat162*)lo)[2 * i + 1] = __nv_bfloat162(l2, l3);
}

// ---------------------------------------------------------------------------
// HMMA GEMM: out[4096,768] = (A @ W^T + bias)*scale, bf16x3 split.
// CTA 128x128, 8 warps (warp tile 32x64), K-chunk 64 in SW128-swizzled smem.
// layout 0: row-major [M,768]; layout 1: [B,H,S,64] with col = h*64+d.
// ---------------------------------------------------------------------------
#define OFF_AH 0u
#define OFF_AL 16384u
#define OFF_BH 32768u
#define OFF_BL 49152u
#define GEMM_SMEM 65536

__global__ void __launch_bounds__(256, 1) tc_gemm_kernel(
    const __nv_bfloat16* __restrict__ Ah, const __nv_bfloat16* __restrict__ Al,
    const __nv_bfloat16* __restrict__ Bh, const __nv_bfloat16* __restrict__ Bl,
    const float* __restrict__ bias, float* __restrict__ out,
    float scale, int layout)
{
    extern __shared__ __align__(16) char smem[];
    const uint32_t sb = smem_to_u32(smem);
    const int tid    = threadIdx.x;
    const int lane   = tid & 31;
    const int wid    = tid >> 5;
    const int warp_m = wid & 3;    // 4 warps over M: 32 rows each
    const int warp_n = wid >> 2;   // 2 warps over N: 64 cols each
    const int bm = blockIdx.y * 128;
    const int bn = blockIdx.x * 128;

    float acc[2][8][4];
#pragma unroll
    for (int mi = 0; mi < 2; mi++)
#pragma unroll
        for (int nj = 0; nj < 8; nj++)
#pragma unroll
            for (int c = 0; c < 4; c++) acc[mi][nj][c] = 0.0f;

    // ldmatrix lane addressing (swizzled rows of 64 bf16 = 128B)
    const int a_row  = warp_m * 32 + (lane & 15);       // + mi*16
    const int a_chalf = lane >> 4;                      // k 16B-chunk half
    const int b_nloc = warp_n * 64 + (lane & 7) + ((lane >> 4) << 3);  // + np*16
    const int b_chalf = (lane >> 3) & 1;
    const int rm8 = lane & 7;                           // row % 8 for swizzle

    for (int k0 = 0; k0 < DMODEL; k0 += 64) {
        // Stage 4 tiles of 128x64 bf16, SW128-style swizzle (chunk ^= row&7)
#pragma unroll
        for (int i = tid; i < 1024; i += 256) {
            const int r = i >> 3;
            const int c = i & 7;
            const uint32_t so = (uint32_t)(r * 128 + ((c ^ (r & 7)) << 4));
            const size_t ga = (size_t)(bm + r) * DMODEL + k0 + c * 8;
            const size_t gb = (size_t)(bn + r) * DMODEL + k0 + c * 8;
            *(uint4*)(smem + OFF_AH + so) = *(const uint4*)(Ah + ga);
            *(uint4*)(smem + OFF_AL + so) = *(const uint4*)(Al + ga);
            *(uint4*)(smem + OFF_BH + so) = *(const uint4*)(Bh + gb);
            *(uint4*)(smem + OFF_BL + so) = *(const uint4*)(Bl + gb);
        }
        __syncthreads();

#pragma unroll
        for (int ks = 0; ks < 4; ks++) {
            // A fragments (hi, lo) for both m16 tiles
            uint32_t ah[2][4], al[2][4];
#pragma unroll
            for (int mi = 0; mi < 2; mi++) {
                const int row = a_row + mi * 16;
                const uint32_t co = (uint32_t)(((ks * 2 + a_chalf) ^ rm8) << 4);
                ldsm_x4(ah[mi][0], ah[mi][1], ah[mi][2], ah[mi][3],
                        sb + OFF_AH + row * 128 + co);
                ldsm_x4(al[mi][0], al[mi][1], al[mi][2], al[mi][3],
                        sb + OFF_AL + row * 128 + co);
            }
#pragma unroll
            for (int np = 0; np < 4; np++) {
                const int nrow = b_nloc + np * 16;
                const uint32_t co = (uint32_t)(((ks * 2 + b_chalf) ^ rm8) << 4);
                uint32_t bh0, bh1, bh2, bh3, bl0, bl1, bl2, bl3;
                ldsm_x4(bh0, bh1, bh2, bh3, sb + OFF_BH + nrow * 128 + co);
                ldsm_x4(bl0, bl1, bl2, bl3, sb + OFF_BL + nrow * 128 + co);
#pragma unroll
                for (int mi = 0; mi < 2; mi++) {
                    mma_bf16(acc[mi][np * 2],     ah[mi], bh0, bh1);
                    mma_bf16(acc[mi][np * 2],     ah[mi], bl0, bl1);
                    mma_bf16(acc[mi][np * 2],     al[mi], bh0, bh1);
                    mma_bf16(acc[mi][np * 2 + 1], ah[mi], bh2, bh3);
                    mma_bf16(acc[mi][np * 2 + 1], ah[mi], bl2, bl3);
                    mma_bf16(acc[mi][np * 2 + 1], al[mi], bh2, bh3);
                }
            }
        }
        __syncthreads();
    }

    // Epilogue: c0/c1 at (row, nc..nc+1), c2/c3 at (row+8, nc..nc+1)
    const int erow = bm + warp_m * 32 + (lane >> 2);
    const int ecol = bn + warp_n * 64 + (lane & 3) * 2;
#pragma unroll
    for (int mi = 0; mi < 2; mi++) {
#pragma unroll
        for (int nj = 0; nj < 8; nj++) {
            const int gc = ecol + nj * 8;
            const float b0 = bias[gc], b1 = bias[gc + 1];
#pragma unroll
            for (int half = 0; half < 2; half++) {
                const int gr = erow + mi * 16 + half * 8;
                const float v0 = (acc[mi][nj][half * 2]     + b0) * scale;
                const float v1 = (acc[mi][nj][half * 2 + 1] + b1) * scale;
                if (layout == 0) {
                    *(float2*)(out + (size_t)gr * DMODEL + gc) = make_float2(v0, v1);
                } else {
                    const int b = gr >> 11, s = gr & 2047;
                    const int h = gc >> 6,  d = gc & 63;
                    *(float2*)(out + (((size_t)b * HNUM + h) * SEQ + s) * DK + d) =
                        make_float2(v0, v1);
                }
            }
        }
    }
}

// ---------------------------------------------------------------------------
// Fused flash-style attention (unchanged from passing round)
// ---------------------------------------------------------------------------
#define ASTR 68

__global__ void __launch_bounds__(256) attn_kernel(
    const float* __restrict__ Q, const float* __restrict__ K,
    const float* __restrict__ V, const int* __restrict__ mask,
    float* __restrict__ out)
{
    extern __shared__ __align__(16) float sm[];
    float* Qs  = sm;
    float* KVs = sm + 64 * ASTR;
    float* Ps  = sm + 2 * 64 * ASTR;
    __shared__ int msk[64];

    const int t  = threadIdx.x;
    const int ty = t >> 4;
    const int tx = t & 15;
    const int bh = blockIdx.y;
    const int b  = bh / HNUM;
    const int h  = bh % HNUM;
    const int q0 = blockIdx.x * 64;

    const float* Qbase = Q + ((size_t)bh * SEQ + q0) * DK;
    const float* Kbase = K + (size_t)bh * SEQ * DK;
    const float* Vbase = V + (size_t)bh * SEQ * DK;

    for (int idx = t; idx < 64 * 16; idx += 256) {
        const int r = idx >> 4;
        const int c = (idx & 15) << 2;
        *(float4*)(&Qs[r * ASTR + c]) = *(const float4*)(Qbase + r * DK + c);
    }

    float o[4][4];
    float mreg[4], lreg[4];
#pragma unroll
    for (int i = 0; i < 4; i++) {
        mreg[i] = -1e30f;
        lreg[i] = 0.0f;
#pragma unroll
        for (int j = 0; j < 4; j++) o[i][j] = 0.0f;
    }

    for (int j0 = 0; j0 < SEQ; j0 += 64) {
        for (int idx = t; idx < 64 * 16; idx += 256) {
            const int r = idx >> 4;
            const int c = (idx & 15) << 2;
            *(float4*)(&KVs[r * ASTR + c]) =
                *(const float4*)(Kbase + (size_t)(j0 + r) * DK + c);
        }
        if (t < 64) msk[t] = mask[b * SEQ + j0 + t];
        __syncthreads();

        float s[4][4];
#pragma unroll
        for (int i = 0; i < 4; i++)
#pragma unroll
            for (int j = 0; j < 4; j++) s[i][j] = 0.0f;

        for (int d = 0; d < DK; d += 4) {
            float4 qa[4], kb[4];
#pragma unroll
            for (int i = 0; i < 4; i++)
                qa[i] = *(const float4*)(&Qs[(ty * 4 + i) * ASTR + d]);
#pragma unroll
            for (int j = 0; j < 4; j++)
                kb[j] = *(const float4*)(&KVs[(tx * 4 + j) * ASTR + d]);
#pragma unroll
            for (int i = 0; i < 4; i++)
#pragma unroll
                for (int j = 0; j < 4; j++) {
                    s[i][j] = fmaf(qa[i].x, kb[j].x, s[i][j]);
                    s[i][j] = fmaf(qa[i].y, kb[j].y, s[i][j]);
                    s[i][j] = fmaf(qa[i].z, kb[j].z, s[i][j]);
                    s[i][j] = fmaf(qa[i].w, kb[j].w, s[i][j]);
                }
        }

#pragma unroll
        for (int j = 0; j < 4; j++) {
            if (msk[tx * 4 + j] == 0) {
#pragma unroll
                for (int i = 0; i < 4; i++) s[i][j] = -1e9f;
            }
        }

#pragma unroll
        for (int i = 0; i < 4; i++) {
            float tm = fmaxf(fmaxf(s[i][0], s[i][1]), fmaxf(s[i][2], s[i][3]));
#pragma unroll
            for (int off = 8; off >= 1; off >>= 1)
                tm = fmaxf(tm, __shfl_xor_sync(0xffffffffu, tm, off, 16));
            const float mn    = fmaxf(mreg[i], tm);
            const float alpha = __expf(mreg[i] - mn);
            mreg[i] = mn;
            float rs = 0.0f;
#pragma unroll
            for (int j = 0; j < 4; j++) {
                const float p = __expf(s[i][j] - mn);
                s[i][j] = p;
                rs += p;
            }
#pragma unroll
            for (int off = 8; off >= 1; off >>= 1)
                rs += __shfl_xor_sync(0xffffffffu, rs, off, 16);
            lreg[i] = lreg[i] * alpha + rs;
#pragma unroll
            for (int j = 0; j < 4; j++) o[i][j] *= alpha;
        }

#pragma unroll
        for (int i = 0; i < 4; i++) {
            float4 p4 = make_float4(s[i][0], s[i][1], s[i][2], s[i][3]);
            *(float4*)(&Ps[(ty * 4 + i) * ASTR + tx * 4]) = p4;
        }
        __syncthreads();

        for (int idx = t; idx < 64 * 16; idx += 256) {
            const int r = idx >> 4;
            const int c = (idx & 15) << 2;
            *(float4*)(&KVs[r * ASTR + c]) =
                *(const float4*)(Vbase + (size_t)(j0 + r) * DK + c);
        }
        __syncthreads();

        for (int kk = 0; kk < 64; kk += 4) {
            float4 pv[4], vv[4];
#pragma unroll
            for (int i = 0; i < 4; i++)
                pv[i] = *(const float4*)(&Ps[(ty * 4 + i) * ASTR + kk]);
#pragma unroll
            for (int u = 0; u < 4; u++)
                vv[u] = *(const float4*)(&KVs[(kk + u) * ASTR + tx * 4]);
#pragma unroll
            for (int i = 0; i < 4; i++) {
                const float pc[4] = {pv[i].x, pv[i].y, pv[i].z, pv[i].w};
#pragma unroll
                for (int u = 0; u < 4; u++) {
                    o[i][0] = fmaf(pc[u], vv[u].x, o[i][0]);
                    o[i][1] = fmaf(pc[u], vv[u].y, o[i][1]);
                    o[i][2] = fmaf(pc[u], vv[u].z, o[i][2]);
                    o[i][3] = fmaf(pc[u], vv[u].w, o[i][3]);
                }
            }
        }
        __syncthreads();
    }

#pragma unroll
    for (int i = 0; i < 4; i++) {
        const float inv = 1.0f / lreg[i];
        const int srow  = q0 + ty * 4 + i;
        float* orow = out + (((size_t)b * SEQ + srow) * HNUM + h) * DK + tx * 4;
        float4 o4 = make_float4(o[i][0] * inv, o[i][1] * inv,
                                o[i][2] * inv, o[i][3] * inv);
        *(float4*)orow = o4;
    }
}

// ---------------------------------------------------------------------------
// Launch
// ---------------------------------------------------------------------------
extern "C" void kernel_launch(void* const* d_in, const int* in_sizes, int n_in,
                              void* d_out, int out_size)
{
    const float* query = (const float*)d_in[0];
    const float* key   = (const float*)d_in[1];
    const float* value = (const float*)d_in[2];
    const int*   mask  = (const int*)  d_in[3];
    const float* Wq    = (const float*)d_in[4];
    const float* bq    = (const float*)d_in[5];
    const float* Wk    = (const float*)d_in[6];
    const float* bk    = (const float*)d_in[7];
    const float* Wv    = (const float*)d_in[8];
    const float* bv    = (const float*)d_in[9];
    const float* Wo    = (const float*)d_in[10];
    const float* bo    = (const float*)d_in[11];

    float *qb, *kb, *vb, *ab;
    __nv_bfloat16 *ah, *al, *wh, *wl, *oh, *ol;
    cudaGetSymbolAddress((void**)&qb, g_q);
    cudaGetSymbolAddress((void**)&kb, g_k);
    cudaGetSymbolAddress((void**)&vb, g_v);
    cudaGetSymbolAddress((void**)&ab, g_ao);
    cudaGetSymbolAddress((void**)&ah, g_ah);
    cudaGetSymbolAddress((void**)&al, g_al);
    cudaGetSymbolAddress((void**)&wh, g_wh);
    cudaGetSymbolAddress((void**)&wl, g_wl);
    cudaGetSymbolAddress((void**)&oh, g_oh);
    cudaGetSymbolAddress((void**)&ol, g_ol);

    const int attn_smem = 3 * 64 * ASTR * (int)sizeof(float);
    cudaFuncSetAttribute(attn_kernel,
                         cudaFuncAttributeMaxDynamicSharedMemorySize, attn_smem);
    cudaFuncSetAttribute(tc_gemm_kernel,
                         cudaFuncAttributeMaxDynamicSharedMemorySize, GEMM_SMEM);

    const int NA = MTOT * DMODEL;       // 3145728
    const int NW = DMODEL * DMODEL;     // 589824
    const int a4 = NA / 4, w4 = NW / 4;

    cvt_split_kernel<<<(a4 + 255) / 256, 256>>>(query, ah,          al,          a4);
    cvt_split_kernel<<<(a4 + 255) / 256, 256>>>(key,   ah + NA,     al + NA,     a4);
    cvt_split_kernel<<<(a4 + 255) / 256, 256>>>(value, ah + 2 * NA, al + 2 * NA, a4);
    cvt_split_kernel<<<(w4 + 255) / 256, 256>>>(Wq, wh,          wl,          w4);
    cvt_split_kernel<<<(w4 + 255) / 256, 256>>>(Wk, wh + NW,     wl + NW,     w4);
    cvt_split_kernel<<<(w4 + 255) / 256, 256>>>(Wv, wh + 2 * NW, wl + 2 * NW, w4);
    cvt_split_kernel<<<(w4 + 255) / 256, 256>>>(Wo, wh + 3 * NW, wl + 3 * NW, w4);

    dim3 ggrid(DMODEL / 128, MTOT / 128);   // (6, 32)
    tc_gemm_kernel<<<ggrid, 256, GEMM_SMEM>>>(ah,          al,          wh,          wl,          bq, qb, 0.125f, 1);
    tc_gemm_kernel<<<ggrid, 256, GEMM_SMEM>>>(ah + NA,     al + NA,     wh + NW,     wl + NW,     bk, kb, 1.0f,   1);
    tc_gemm_kernel<<<ggrid, 256, GEMM_SMEM>>>(ah + 2 * NA, al + 2 * NA, wh + 2 * NW, wl + 2 * NW, bv, vb, 1.0f,   1);

    attn_kernel<<<dim3(SEQ / 64, BATCH * HNUM), 256, attn_smem>>>(
        qb, kb, vb, mask, ab);

    cvt_split_kernel<<<(a4 + 255) / 256, 256>>>(ab, oh, ol, a4);
    tc_gemm_kernel<<<ggrid, 256, GEMM_SMEM>>>(oh, ol, wh + 3 * NW, wl + 3 * NW, bo, (float*)d_out, 1.0f, 0);
}

// round 5
// speedup vs baseline: 3.0681x; 2.5930x over previous
#include <cuda_runtime.h>
#include <cuda_bf16.h>
#include <cstdint>
#include <math.h>

#define HNUM   12
#define DMODEL 768
#define BATCH  2
#define SEQ    2048
#define DK     64
#define MTOT   (BATCH * SEQ)          // 4096

// ---------------------------------------------------------------------------
// Scratch (allocation-free): everything bf16 hi/lo
// ---------------------------------------------------------------------------
__device__ __nv_bfloat16 g_qh[BATCH * HNUM * SEQ * DK];
__device__ __nv_bfloat16 g_ql[BATCH * HNUM * SEQ * DK];
__device__ __nv_bfloat16 g_kh[BATCH * HNUM * SEQ * DK];
__device__ __nv_bfloat16 g_kl[BATCH * HNUM * SEQ * DK];
__device__ __nv_bfloat16 g_vh[BATCH * HNUM * SEQ * DK];
__device__ __nv_bfloat16 g_vl[BATCH * HNUM * SEQ * DK];

__device__ __nv_bfloat16 g_ah[3 * MTOT * DMODEL];
__device__ __nv_bfloat16 g_al[3 * MTOT * DMODEL];
__device__ __nv_bfloat16 g_wh[4 * DMODEL * DMODEL];
__device__ __nv_bfloat16 g_wl[4 * DMODEL * DMODEL];
__device__ __nv_bfloat16 g_oh[MTOT * DMODEL];
__device__ __nv_bfloat16 g_ol[MTOT * DMODEL];

// ---------------------------------------------------------------------------
// Warp-MMA helpers
// ---------------------------------------------------------------------------
__device__ __forceinline__ uint32_t smem_to_u32(const void* p) {
    uint32_t a;
    asm("{ .reg .u64 t; cvta.to.shared.u64 t, %1; cvt.u32.u64 %0, t; }"
        : "=r"(a) : "l"(p));
    return a;
}

__device__ __forceinline__ void ldsm_x4(uint32_t& r0, uint32_t& r1,
                                        uint32_t& r2, uint32_t& r3, uint32_t addr) {
    asm volatile("ldmatrix.sync.aligned.m8n8.x4.shared.b16 {%0,%1,%2,%3}, [%4];"
                 : "=r"(r0), "=r"(r1), "=r"(r2), "=r"(r3) : "r"(addr));
}
__device__ __forceinline__ void ldsm_x4_t(uint32_t& r0, uint32_t& r1,
                                          uint32_t& r2, uint32_t& r3, uint32_t addr) {
    asm volatile("ldmatrix.sync.aligned.m8n8.x4.trans.shared.b16 {%0,%1,%2,%3}, [%4];"
                 : "=r"(r0), "=r"(r1), "=r"(r2), "=r"(r3) : "r"(addr));
}

__device__ __forceinline__ void mma_bf16(float* c, const uint32_t* a,
                                         uint32_t b0, uint32_t b1) {
    asm volatile("mma.sync.aligned.m16n8k16.row.col.f32.bf16.bf16.f32 "
                 "{%0,%1,%2,%3}, {%4,%5,%6,%7}, {%8,%9}, {%0,%1,%2,%3};"
                 : "+f"(c[0]), "+f"(c[1]), "+f"(c[2]), "+f"(c[3])
                 : "r"(a[0]), "r"(a[1]), "r"(a[2]), "r"(a[3]), "r"(b0), "r"(b1));
}

__device__ __forceinline__ uint32_t pack_bf16(float x, float y) {
    __nv_bfloat162 t = __floats2bfloat162_rn(x, y);
    return *(uint32_t*)&t;
}

// ---------------------------------------------------------------------------
// fp32 -> bf16 hi/lo split (elementwise)
// ---------------------------------------------------------------------------
__global__ void __launch_bounds__(256) cvt_split_kernel(
    const float* __restrict__ x, __nv_bfloat16* __restrict__ hi,
    __nv_bfloat16* __restrict__ lo, int n4)
{
    int i = blockIdx.x * 256 + threadIdx.x;
    if (i >= n4) return;
    float4 v = ((const float4*)x)[i];
    __nv_bfloat16 h0 = __float2bfloat16(v.x), h1 = __float2bfloat16(v.y);
    __nv_bfloat16 h2 = __float2bfloat16(v.z), h3 = __float2bfloat16(v.w);
    __nv_bfloat16 l0 = __float2bfloat16(v.x - __bfloat162float(h0));
    __nv_bfloat16 l1 = __float2bfloat16(v.y - __bfloat162float(h1));
    __nv_bfloat16 l2 = __float2bfloat16(v.z - __bfloat162float(h2));
    __nv_bfloat16 l3 = __float2bfloat16(v.w - __bfloat162float(h3));
    ((__nv_bfloat162*)hi)[2 * i]     = __nv_bfloat162(h0, h1);
    ((__nv_bfloat162*)hi)[2 * i + 1] = __nv_bfloat162(h2, h3);
    ((__nv_bfloat162*)lo)[2 * i]     = __nv_bfloat162(l0, l1);
    ((__nv_bfloat162*)lo)[2 * i + 1] = __nv_bfloat162(l2, l3);
}

// ---------------------------------------------------------------------------
// HMMA GEMM (bf16x3): layout 0 -> fp32 row-major [M,768];
//                     layout 1 -> bf16 hi/lo [B,H,S,64] (col = h*64+d).
// ---------------------------------------------------------------------------
#define OFF_AH 0u
#define OFF_AL 16384u
#define OFF_BH 32768u
#define OFF_BL 49152u
#define GEMM_SMEM 65536

__global__ void __launch_bounds__(256, 1) tc_gemm_kernel(
    const __nv_bfloat16* __restrict__ Ah, const __nv_bfloat16* __restrict__ Al,
    const __nv_bfloat16* __restrict__ Bh, const __nv_bfloat16* __restrict__ Bl,
    const float* __restrict__ bias, float* __restrict__ outf,
    __nv_bfloat16* __restrict__ outh, __nv_bfloat16* __restrict__ outl,
    float scale, int layout)
{
    extern __shared__ __align__(16) char smem[];
    const uint32_t sb = smem_to_u32(smem);
    const int tid    = threadIdx.x;
    const int lane   = tid & 31;
    const int wid    = tid >> 5;
    const int warp_m = wid & 3;
    const int warp_n = wid >> 2;
    const int bm = blockIdx.y * 128;
    const int bn = blockIdx.x * 128;

    float acc[2][8][4];
#pragma unroll
    for (int mi = 0; mi < 2; mi++)
#pragma unroll
        for (int nj = 0; nj < 8; nj++)
#pragma unroll
            for (int c = 0; c < 4; c++) acc[mi][nj][c] = 0.0f;

    const int a_row   = warp_m * 32 + (lane & 15);
    const int a_chalf = lane >> 4;
    const int b_nloc  = warp_n * 64 + (lane & 7) + ((lane >> 4) << 3);
    const int b_chalf = (lane >> 3) & 1;
    const int rm8     = lane & 7;

    for (int k0 = 0; k0 < DMODEL; k0 += 64) {
#pragma unroll
        for (int i = tid; i < 1024; i += 256) {
            const int r = i >> 3;
            const int c = i & 7;
            const uint32_t so = (uint32_t)(r * 128 + ((c ^ (r & 7)) << 4));
            const size_t ga = (size_t)(bm + r) * DMODEL + k0 + c * 8;
            const size_t gb = (size_t)(bn + r) * DMODEL + k0 + c * 8;
            *(uint4*)(smem + OFF_AH + so) = *(const uint4*)(Ah + ga);
            *(uint4*)(smem + OFF_AL + so) = *(const uint4*)(Al + ga);
            *(uint4*)(smem + OFF_BH + so) = *(const uint4*)(Bh + gb);
            *(uint4*)(smem + OFF_BL + so) = *(const uint4*)(Bl + gb);
        }
        __syncthreads();

#pragma unroll
        for (int ks = 0; ks < 4; ks++) {
            uint32_t ah[2][4], al[2][4];
#pragma unroll
            for (int mi = 0; mi < 2; mi++) {
                const int row = a_row + mi * 16;
                const uint32_t co = (uint32_t)(((ks * 2 + a_chalf) ^ rm8) << 4);
                ldsm_x4(ah[mi][0], ah[mi][1], ah[mi][2], ah[mi][3],
                        sb + OFF_AH + row * 128 + co);
                ldsm_x4(al[mi][0], al[mi][1], al[mi][2], al[mi][3],
                        sb + OFF_AL + row * 128 + co);
            }
#pragma unroll
            for (int np = 0; np < 4; np++) {
                const int nrow = b_nloc + np * 16;
                const uint32_t co = (uint32_t)(((ks * 2 + b_chalf) ^ rm8) << 4);
                uint32_t bh0, bh1, bh2, bh3, bl0, bl1, bl2, bl3;
                ldsm_x4(bh0, bh1, bh2, bh3, sb + OFF_BH + nrow * 128 + co);
                ldsm_x4(bl0, bl1, bl2, bl3, sb + OFF_BL + nrow * 128 + co);
#pragma unroll
                for (int mi = 0; mi < 2; mi++) {
                    mma_bf16(acc[mi][np * 2],     ah[mi], bh0, bh1);
                    mma_bf16(acc[mi][np * 2],     ah[mi], bl0, bl1);
                    mma_bf16(acc[mi][np * 2],     al[mi], bh0, bh1);
                    mma_bf16(acc[mi][np * 2 + 1], ah[mi], bh2, bh3);
                    mma_bf16(acc[mi][np * 2 + 1], ah[mi], bl2, bl3);
                    mma_bf16(acc[mi][np * 2 + 1], al[mi], bh2, bh3);
                }
            }
        }
        __syncthreads();
    }

    const int erow = bm + warp_m * 32 + (lane >> 2);
    const int ecol = bn + warp_n * 64 + (lane & 3) * 2;
#pragma unroll
    for (int mi = 0; mi < 2; mi++) {
#pragma unroll
        for (int nj = 0; nj < 8; nj++) {
            const int gc = ecol + nj * 8;
            const float b0 = bias[gc], b1 = bias[gc + 1];
#pragma unroll
            for (int half = 0; half < 2; half++) {
                const int gr = erow + mi * 16 + half * 8;
                const float v0 = (acc[mi][nj][half * 2]     + b0) * scale;
                const float v1 = (acc[mi][nj][half * 2 + 1] + b1) * scale;
                if (layout == 0) {
                    *(float2*)(outf + (size_t)gr * DMODEL + gc) = make_float2(v0, v1);
                } else {
                    const int b = gr >> 11, s = gr & 2047;
                    const int h = gc >> 6,  d = gc & 63;
                    const size_t oi = (((size_t)b * HNUM + h) * SEQ + s) * DK + d;
                    __nv_bfloat16 h0 = __float2bfloat16(v0), h1 = __float2bfloat16(v1);
                    __nv_bfloat16 e0 = __float2bfloat16(v0 - __bfloat162float(h0));
                    __nv_bfloat16 e1 = __float2bfloat16(v1 - __bfloat162float(h1));
                    *(__nv_bfloat162*)(outh + oi) = __nv_bfloat162(h0, h1);
                    *(__nv_bfloat162*)(outl + oi) = __nv_bfloat162(e0, e1);
                }
            }
        }
    }
}

// ---------------------------------------------------------------------------
// MMA flash attention: CTA = 128 q-rows x (b,h); KV blocks of 128.
// 8 warps x 16 q-rows. bf16x3 split for QK^T and PV. P stays in registers.
// Output written as bf16 hi/lo [B,S,H*64].
// ---------------------------------------------------------------------------
#define AT_KH 0u
#define AT_KL 16384u
#define AT_VH 32768u
#define AT_VL 49152u
#define ATTN_SMEM 65536

__global__ void __launch_bounds__(256, 1) attn_mma_kernel(
    const __nv_bfloat16* __restrict__ Qh, const __nv_bfloat16* __restrict__ Ql,
    const __nv_bfloat16* __restrict__ Kh, const __nv_bfloat16* __restrict__ Kl,
    const __nv_bfloat16* __restrict__ Vh, const __nv_bfloat16* __restrict__ Vl,
    const int* __restrict__ mask,
    __nv_bfloat16* __restrict__ Oh, __nv_bfloat16* __restrict__ Ol)
{
    extern __shared__ __align__(16) char smem[];
    __shared__ int msk[128];
    const uint32_t sb = smem_to_u32(smem);
    const int tid = threadIdx.x, lane = tid & 31, wid = tid >> 5;
    const int bh = blockIdx.y, b = bh / HNUM, h = bh % HNUM;
    const int q0 = blockIdx.x * 128;
    const size_t hb = (size_t)bh * SEQ * DK;
    const int rm8 = lane & 7;

    // Stage Q tile (128x64 hi/lo) into K area, pull fragments to registers
    for (int i = tid; i < 1024; i += 256) {
        const int r = i >> 3, c = i & 7;
        const uint32_t so = (uint32_t)(r * 128 + ((c ^ (r & 7)) << 4));
        const size_t g = hb + (size_t)(q0 + r) * DK + c * 8;
        *(uint4*)(smem + AT_KH + so) = *(const uint4*)(Qh + g);
        *(uint4*)(smem + AT_KL + so) = *(const uint4*)(Ql + g);
    }
    __syncthreads();

    const int arow = wid * 16 + (lane & 15);
    const int ach  = lane >> 4;
    uint32_t qfh[4][4], qfl[4][4];
#pragma unroll
    for (int ks = 0; ks < 4; ks++) {
        const uint32_t co = (uint32_t)(((ks * 2 + ach) ^ rm8) << 4);
        ldsm_x4(qfh[ks][0], qfh[ks][1], qfh[ks][2], qfh[ks][3],
                sb + AT_KH + arow * 128 + co);
        ldsm_x4(qfl[ks][0], qfl[ks][1], qfl[ks][2], qfl[ks][3],
                sb + AT_KL + arow * 128 + co);
    }
    __syncthreads();

    float oacc[8][4];
#pragma unroll
    for (int nj = 0; nj < 8; nj++)
#pragma unroll
        for (int c = 0; c < 4; c++) oacc[nj][c] = 0.0f;
    float mr0 = -1e30f, mr1 = -1e30f, lr0 = 0.0f, lr1 = 0.0f;

    const int knloc = (lane & 7) + ((lane >> 4) << 3);
    const int kch   = (lane >> 3) & 1;
    const int vrow_base = (lane & 7) + (((lane >> 3) & 1) << 3);
    const int vch   = lane >> 4;
    const int c0i   = 2 * (lane & 3);

    for (int j0 = 0; j0 < SEQ; j0 += 128) {
        for (int i = tid; i < 1024; i += 256) {
            const int r = i >> 3, c = i & 7;
            const uint32_t so = (uint32_t)(r * 128 + ((c ^ (r & 7)) << 4));
            const size_t g = hb + (size_t)(j0 + r) * DK + c * 8;
            *(uint4*)(smem + AT_KH + so) = *(const uint4*)(Kh + g);
            *(uint4*)(smem + AT_KL + so) = *(const uint4*)(Kl + g);
            *(uint4*)(smem + AT_VH + so) = *(const uint4*)(Vh + g);
            *(uint4*)(smem + AT_VL + so) = *(const uint4*)(Vl + g);
        }
        if (tid < 128) msk[tid] = mask[b * SEQ + j0 + tid];
        __syncthreads();

        // S = Q K^T : 16 n-tiles of 8 keys
        float sacc[16][4];
#pragma unroll
        for (int nj = 0; nj < 16; nj++)
#pragma unroll
            for (int c = 0; c < 4; c++) sacc[nj][c] = 0.0f;

#pragma unroll
        for (int ks = 0; ks < 4; ks++) {
            const uint32_t co = (uint32_t)(((ks * 2 + kch) ^ rm8) << 4);
#pragma unroll
            for (int np = 0; np < 8; np++) {
                const int nrow = np * 16 + knloc;
                uint32_t h0, h1, h2, h3, l0, l1, l2, l3;
                ldsm_x4(h0, h1, h2, h3, sb + AT_KH + nrow * 128 + co);
                ldsm_x4(l0, l1, l2, l3, sb + AT_KL + nrow * 128 + co);
                mma_bf16(sacc[np * 2],     qfh[ks], h0, h1);
                mma_bf16(sacc[np * 2],     qfh[ks], l0, l1);
                mma_bf16(sacc[np * 2],     qfl[ks], h0, h1);
                mma_bf16(sacc[np * 2 + 1], qfh[ks], h2, h3);
                mma_bf16(sacc[np * 2 + 1], qfh[ks], l2, l3);
                mma_bf16(sacc[np * 2 + 1], qfl[ks], h2, h3);
            }
        }

        // Padding mask
#pragma unroll
        for (int nj = 0; nj < 16; nj++) {
            if (msk[nj * 8 + c0i] == 0)     { sacc[nj][0] = -1e9f; sacc[nj][2] = -1e9f; }
            if (msk[nj * 8 + c0i + 1] == 0) { sacc[nj][1] = -1e9f; sacc[nj][3] = -1e9f; }
        }

        // Online softmax (rows lane>>2 and lane>>2+8; stats across quad lanes)
        float m0 = -1e30f, m1 = -1e30f;
#pragma unroll
        for (int nj = 0; nj < 16; nj++) {
            m0 = fmaxf(m0, fmaxf(sacc[nj][0], sacc[nj][1]));
            m1 = fmaxf(m1, fmaxf(sacc[nj][2], sacc[nj][3]));
        }
        m0 = fmaxf(m0, __shfl_xor_sync(0xffffffffu, m0, 1));
        m0 = fmaxf(m0, __shfl_xor_sync(0xffffffffu, m0, 2));
        m1 = fmaxf(m1, __shfl_xor_sync(0xffffffffu, m1, 1));
        m1 = fmaxf(m1, __shfl_xor_sync(0xffffffffu, m1, 2));
        const float mn0 = fmaxf(mr0, m0), mn1 = fmaxf(mr1, m1);
        const float al0 = __expf(mr0 - mn0), al1 = __expf(mr1 - mn1);
        mr0 = mn0; mr1 = mn1;

        float rs0 = 0.0f, rs1 = 0.0f;
        uint32_t phi[16][2], plo[16][2];
#pragma unroll
        for (int nj = 0; nj < 16; nj++) {
            const float p0 = __expf(sacc[nj][0] - mn0);
            const float p1 = __expf(sacc[nj][1] - mn0);
            const float p2 = __expf(sacc[nj][2] - mn1);
            const float p3 = __expf(sacc[nj][3] - mn1);
            rs0 += p0 + p1; rs1 += p2 + p3;
            const float h0 = __bfloat162float(__float2bfloat16(p0));
            const float h1 = __bfloat162float(__float2bfloat16(p1));
            const float h2 = __bfloat162float(__float2bfloat16(p2));
            const float h3 = __bfloat162float(__float2bfloat16(p3));
            phi[nj][0] = pack_bf16(h0, h1);
            phi[nj][1] = pack_bf16(h2, h3);
            plo[nj][0] = pack_bf16(p0 - h0, p1 - h1);
            plo[nj][1] = pack_bf16(p2 - h2, p3 - h3);
        }
        rs0 += __shfl_xor_sync(0xffffffffu, rs0, 1);
        rs0 += __shfl_xor_sync(0xffffffffu, rs0, 2);
        rs1 += __shfl_xor_sync(0xffffffffu, rs1, 1);
        rs1 += __shfl_xor_sync(0xffffffffu, rs1, 2);
        lr0 = lr0 * al0 + rs0;
        lr1 = lr1 * al1 + rs1;

#pragma unroll
        for (int nj = 0; nj < 8; nj++) {
            oacc[nj][0] *= al0; oacc[nj][1] *= al0;
            oacc[nj][2] *= al1; oacc[nj][3] *= al1;
        }

        // O += P @ V  (V via trans ldmatrix)
#pragma unroll
        for (int kt = 0; kt < 8; kt++) {
            uint32_t pah[4] = { phi[2 * kt][0], phi[2 * kt][1],
                                phi[2 * kt + 1][0], phi[2 * kt + 1][1] };
            uint32_t pal[4] = { plo[2 * kt][0], plo[2 * kt][1],
                                plo[2 * kt + 1][0], plo[2 * kt + 1][1] };
            const int vrow = kt * 16 + vrow_base;
#pragma unroll
            for (int np = 0; np < 4; np++) {
                const uint32_t co = (uint32_t)(((np * 2 + vch) ^ rm8) << 4);
                uint32_t h0, h1, h2, h3, l0, l1, l2, l3;
                ldsm_x4_t(h0, h1, h2, h3, sb + AT_VH + vrow * 128 + co);
                ldsm_x4_t(l0, l1, l2, l3, sb + AT_VL + vrow * 128 + co);
                mma_bf16(oacc[np * 2],     pah, h0, h1);
                mma_bf16(oacc[np * 2],     pah, l0, l1);
                mma_bf16(oacc[np * 2],     pal, h0, h1);
                mma_bf16(oacc[np * 2 + 1], pah, h2, h3);
                mma_bf16(oacc[np * 2 + 1], pah, l2, l3);
                mma_bf16(oacc[np * 2 + 1], pal, h2, h3);
            }
        }
        __syncthreads();
    }

    // Epilogue: normalize, split to bf16 hi/lo, write [B,S,H*64]
    const float inv0 = 1.0f / lr0, inv1 = 1.0f / lr1;
    const int s0 = q0 + wid * 16 + (lane >> 2);
#pragma unroll
    for (int nj = 0; nj < 8; nj++) {
        const int d = nj * 8 + c0i;
#pragma unroll
        for (int half = 0; half < 2; half++) {
            const int s = s0 + half * 8;
            const float v0 = oacc[nj][half * 2]     * (half ? inv1 : inv0);
            const float v1 = oacc[nj][half * 2 + 1] * (half ? inv1 : inv0);
            const size_t oi = (size_t)(b * SEQ + s) * DMODEL + h * DK + d;
            __nv_bfloat16 h0 = __float2bfloat16(v0), h1 = __float2bfloat16(v1);
            __nv_bfloat16 e0 = __float2bfloat16(v0 - __bfloat162float(h0));
            __nv_bfloat16 e1 = __float2bfloat16(v1 - __bfloat162float(h1));
            *(__nv_bfloat162*)(Oh + oi) = __nv_bfloat162(h0, h1);
            *(__nv_bfloat162*)(Ol + oi) = __nv_bfloat162(e0, e1);
        }
    }
}

// ---------------------------------------------------------------------------
// Launch
// ---------------------------------------------------------------------------
extern "C" void kernel_launch(void* const* d_in, const int* in_sizes, int n_in,
                              void* d_out, int out_size)
{
    const float* query = (const float*)d_in[0];
    const float* key   = (const float*)d_in[1];
    const float* value = (const float*)d_in[2];
    const int*   mask  = (const int*)  d_in[3];
    const float* Wq    = (const float*)d_in[4];
    const float* bq    = (const float*)d_in[5];
    const float* Wk    = (const float*)d_in[6];
    const float* bk    = (const float*)d_in[7];
    const float* Wv    = (const float*)d_in[8];
    const float* bv    = (const float*)d_in[9];
    const float* Wo    = (const float*)d_in[10];
    const float* bo    = (const float*)d_in[11];

    __nv_bfloat16 *qh, *ql, *kh, *kl, *vh, *vl, *ah, *al, *wh, *wl, *oh, *ol;
    cudaGetSymbolAddress((void**)&qh, g_qh);
    cudaGetSymbolAddress((void**)&ql, g_ql);
    cudaGetSymbolAddress((void**)&kh, g_kh);
    cudaGetSymbolAddress((void**)&kl, g_kl);
    cudaGetSymbolAddress((void**)&vh, g_vh);
    cudaGetSymbolAddress((void**)&vl, g_vl);
    cudaGetSymbolAddress((void**)&ah, g_ah);
    cudaGetSymbolAddress((void**)&al, g_al);
    cudaGetSymbolAddress((void**)&wh, g_wh);
    cudaGetSymbolAddress((void**)&wl, g_wl);
    cudaGetSymbolAddress((void**)&oh, g_oh);
    cudaGetSymbolAddress((void**)&ol, g_ol);

    cudaFuncSetAttribute(tc_gemm_kernel,
                         cudaFuncAttributeMaxDynamicSharedMemorySize, GEMM_SMEM);
    cudaFuncSetAttribute(attn_mma_kernel,
                         cudaFuncAttributeMaxDynamicSharedMemorySize, ATTN_SMEM);

    const int NA = MTOT * DMODEL;
    const int NW = DMODEL * DMODEL;
    const int a4 = NA / 4, w4 = NW / 4;

    cvt_split_kernel<<<(a4 + 255) / 256, 256>>>(query, ah,          al,          a4);
    cvt_split_kernel<<<(a4 + 255) / 256, 256>>>(key,   ah + NA,     al + NA,     a4);
    cvt_split_kernel<<<(a4 + 255) / 256, 256>>>(value, ah + 2 * NA, al + 2 * NA, a4);
    cvt_split_kernel<<<(w4 + 255) / 256, 256>>>(Wq, wh,          wl,          w4);
    cvt_split_kernel<<<(w4 + 255) / 256, 256>>>(Wk, wh + NW,     wl + NW,     w4);
    cvt_split_kernel<<<(w4 + 255) / 256, 256>>>(Wv, wh + 2 * NW, wl + 2 * NW, w4);
    cvt_split_kernel<<<(w4 + 255) / 256, 256>>>(Wo, wh + 3 * NW, wl + 3 * NW, w4);

    dim3 ggrid(DMODEL / 128, MTOT / 128);   // (6, 32)
    tc_gemm_kernel<<<ggrid, 256, GEMM_SMEM>>>(ah,          al,          wh,          wl,          bq, nullptr, qh, ql, 0.125f, 1);
    tc_gemm_kernel<<<ggrid, 256, GEMM_SMEM>>>(ah + NA,     al + NA,     wh + NW,     wl + NW,     bk, nullptr, kh, kl, 1.0f,   1);
    tc_gemm_kernel<<<ggrid, 256, GEMM_SMEM>>>(ah + 2 * NA, al + 2 * NA, wh + 2 * NW, wl + 2 * NW, bv, nullptr, vh, vl, 1.0f,   1);

    attn_mma_kernel<<<dim3(SEQ / 128, BATCH * HNUM), 256, ATTN_SMEM>>>(
        qh, ql, kh, kl, vh, vl, mask, oh, ol);

    tc_gemm_kernel<<<ggrid, 256, GEMM_SMEM>>>(oh, ol, wh + 3 * NW, wl + 3 * NW, bo, (float*)d_out, nullptr, nullptr, 1.0f, 0);
}

// round 6
// speedup vs baseline: 4.4359x; 1.4458x over previous
#include <cuda_runtime.h>
#include <cuda_bf16.h>
#include <cstdint>
#include <math.h>

#define HNUM   12
#define DMODEL 768
#define BATCH  2
#define SEQ    2048
#define DK     64
#define MTOT   (BATCH * SEQ)          // 4096
#define NA_ (MTOT * DMODEL)           // 3145728
#define NW_ (DMODEL * DMODEL)         // 589824

// ---------------------------------------------------------------------------
// Scratch (allocation-free): everything bf16 hi/lo
// ---------------------------------------------------------------------------
__device__ __nv_bfloat16 g_qh[BATCH * HNUM * SEQ * DK];
__device__ __nv_bfloat16 g_ql[BATCH * HNUM * SEQ * DK];
__device__ __nv_bfloat16 g_kh[BATCH * HNUM * SEQ * DK];
__device__ __nv_bfloat16 g_kl[BATCH * HNUM * SEQ * DK];
__device__ __nv_bfloat16 g_vh[BATCH * HNUM * SEQ * DK];
__device__ __nv_bfloat16 g_vl[BATCH * HNUM * SEQ * DK];

__device__ __nv_bfloat16 g_ah[3 * NA_];
__device__ __nv_bfloat16 g_al[3 * NA_];
__device__ __nv_bfloat16 g_wh[4 * NW_];
__device__ __nv_bfloat16 g_wl[4 * NW_];
__device__ __nv_bfloat16 g_oh[NA_];
__device__ __nv_bfloat16 g_ol[NA_];

// ---------------------------------------------------------------------------
// Helpers
// ---------------------------------------------------------------------------
__device__ __forceinline__ uint32_t smem_to_u32(const void* p) {
    uint32_t a;
    asm("{ .reg .u64 t; cvta.to.shared.u64 t, %1; cvt.u32.u64 %0, t; }"
        : "=r"(a) : "l"(p));
    return a;
}
__device__ __forceinline__ void cp16(uint32_t s, const void* g) {
    asm volatile("cp.async.cg.shared.global [%0], [%1], 16;" :: "r"(s), "l"(g));
}
#define CP_COMMIT() asm volatile("cp.async.commit_group;" ::: "memory")
#define CP_WAIT1()  asm volatile("cp.async.wait_group 1;" ::: "memory")
#define CP_WAIT0()  asm volatile("cp.async.wait_group 0;" ::: "memory")

__device__ __forceinline__ void ldsm_x4(uint32_t& r0, uint32_t& r1,
                                        uint32_t& r2, uint32_t& r3, uint32_t addr) {
    asm volatile("ldmatrix.sync.aligned.m8n8.x4.shared.b16 {%0,%1,%2,%3}, [%4];"
                 : "=r"(r0), "=r"(r1), "=r"(r2), "=r"(r3) : "r"(addr));
}
__device__ __forceinline__ void ldsm_x4_t(uint32_t& r0, uint32_t& r1,
                                          uint32_t& r2, uint32_t& r3, uint32_t addr) {
    asm volatile("ldmatrix.sync.aligned.m8n8.x4.trans.shared.b16 {%0,%1,%2,%3}, [%4];"
                 : "=r"(r0), "=r"(r1), "=r"(r2), "=r"(r3) : "r"(addr));
}
__device__ __forceinline__ void mma_bf16(float* c, const uint32_t* a,
                                         uint32_t b0, uint32_t b1) {
    asm volatile("mma.sync.aligned.m16n8k16.row.col.f32.bf16.bf16.f32 "
                 "{%0,%1,%2,%3}, {%4,%5,%6,%7}, {%8,%9}, {%0,%1,%2,%3};"
                 : "+f"(c[0]), "+f"(c[1]), "+f"(c[2]), "+f"(c[3])
                 : "r"(a[0]), "r"(a[1]), "r"(a[2]), "r"(a[3]), "r"(b0), "r"(b1));
}
__device__ __forceinline__ uint32_t pack_bf16(float x, float y) {
    __nv_bfloat162 t = __floats2bfloat162_rn(x, y);
    return *(uint32_t*)&t;
}

// ---------------------------------------------------------------------------
// Fused fp32 -> bf16 hi/lo split; blockIdx.y selects tensor
// ---------------------------------------------------------------------------
__global__ void __launch_bounds__(256) cvt_split_kernel(
    const float* x0, const float* x1, const float* x2, const float* x3,
    __nv_bfloat16* h0p, __nv_bfloat16* h1p, __nv_bfloat16* h2p, __nv_bfloat16* h3p,
    __nv_bfloat16* l0p, __nv_bfloat16* l1p, __nv_bfloat16* l2p, __nv_bfloat16* l3p,
    int n4)
{
    const int z = blockIdx.y;
    const float* x = (z == 0) ? x0 : (z == 1) ? x1 : (z == 2) ? x2 : x3;
    __nv_bfloat16* hi = (z == 0) ? h0p : (z == 1) ? h1p : (z == 2) ? h2p : h3p;
    __nv_bfloat16* lo = (z == 0) ? l0p : (z == 1) ? l1p : (z == 2) ? l2p : l3p;
    int i = blockIdx.x * 256 + threadIdx.x;
    if (i >= n4) return;
    float4 v = ((const float4*)x)[i];
    __nv_bfloat16 h0 = __float2bfloat16(v.x), h1 = __float2bfloat16(v.y);
    __nv_bfloat16 h2 = __float2bfloat16(v.z), h3 = __float2bfloat16(v.w);
    __nv_bfloat16 l0 = __float2bfloat16(v.x - __bfloat162float(h0));
    __nv_bfloat16 l1 = __float2bfloat16(v.y - __bfloat162float(h1));
    __nv_bfloat16 l2 = __float2bfloat16(v.z - __bfloat162float(h2));
    __nv_bfloat16 l3 = __float2bfloat16(v.w - __bfloat162float(h3));
    ((__nv_bfloat162*)hi)[2 * i]     = __nv_bfloat162(h0, h1);
    ((__nv_bfloat162*)hi)[2 * i + 1] = __nv_bfloat162(h2, h3);
    ((__nv_bfloat162*)lo)[2 * i]     = __nv_bfloat162(l0, l1);
    ((__nv_bfloat162*)lo)[2 * i + 1] = __nv_bfloat162(l2, l3);
}

// ---------------------------------------------------------------------------
// HMMA GEMM (bf16x3), cp.async double-buffered.
// qkv_mode=1: blockIdx.z in 0..2 selects (A,W,bias,out-pair); layout [B,H,S,64].
// qkv_mode=0: z=0; fp32 row-major output.
// ---------------------------------------------------------------------------
#define OFF_AH 0u
#define OFF_AL 16384u
#define OFF_BH 32768u
#define OFF_BL 49152u
#define STAGE_SZ 65536u
#define GEMM_SMEM 131072

__global__ void __launch_bounds__(256, 1) tc_gemm_kernel(
    const __nv_bfloat16* Abase_h, const __nv_bfloat16* Abase_l,
    const __nv_bfloat16* Wbase_h, const __nv_bfloat16* Wbase_l,
    const float* bias0, const float* bias1, const float* bias2,
    float* outf,
    __nv_bfloat16* o0h, __nv_bfloat16* o0l,
    __nv_bfloat16* o1h, __nv_bfloat16* o1l,
    __nv_bfloat16* o2h, __nv_bfloat16* o2l,
    int qkv_mode)
{
    extern __shared__ __align__(16) char smem[];
    const uint32_t sb = smem_to_u32(smem);
    const int tid  = threadIdx.x;
    const int lane = tid & 31;
    const int wid  = tid >> 5;
    const int warp_m = wid & 3;
    const int warp_n = wid >> 2;
    const int bm = blockIdx.y * 128;
    const int bn = blockIdx.x * 128;
    const int z  = blockIdx.z;

    const __nv_bfloat16* Ah = Abase_h + (size_t)z * NA_;
    const __nv_bfloat16* Al = Abase_l + (size_t)z * NA_;
    const __nv_bfloat16* Bh = Wbase_h + (size_t)z * NW_;
    const __nv_bfloat16* Bl = Wbase_l + (size_t)z * NW_;
    const float* bias = (z == 0) ? bias0 : (z == 1) ? bias1 : bias2;
    const float scale = (qkv_mode && z == 0) ? 0.125f : 1.0f;
    __nv_bfloat16* outh = (z == 0) ? o0h : (z == 1) ? o1h : o2h;
    __nv_bfloat16* outl = (z == 0) ? o0l : (z == 1) ? o1l : o2l;

    float acc[2][8][4];
#pragma unroll
    for (int mi = 0; mi < 2; mi++)
#pragma unroll
        for (int nj = 0; nj < 8; nj++)
#pragma unroll
            for (int c = 0; c < 4; c++) acc[mi][nj][c] = 0.0f;

    const int a_row   = warp_m * 32 + (lane & 15);
    const int a_chalf = lane >> 4;
    const int b_nloc  = warp_n * 64 + (lane & 7) + ((lane >> 4) << 3);
    const int b_chalf = (lane >> 3) & 1;
    const int rm8     = lane & 7;

    // prefetch of K-chunk ch into stage st
    auto prefetch = [&](int ch, int st) {
        const uint32_t base = sb + st * STAGE_SZ;
        const int k0 = ch * 64;
#pragma unroll
        for (int i = tid; i < 1024; i += 256) {
            const int r = i >> 3, c = i & 7;
            const uint32_t so = (uint32_t)(r * 128 + ((c ^ (r & 7)) << 4));
            const size_t ga = (size_t)(bm + r) * DMODEL + k0 + c * 8;
            const size_t gb = (size_t)(bn + r) * DMODEL + k0 + c * 8;
            cp16(base + OFF_AH + so, Ah + ga);
            cp16(base + OFF_AL + so, Al + ga);
            cp16(base + OFF_BH + so, Bh + gb);
            cp16(base + OFF_BL + so, Bl + gb);
        }
        CP_COMMIT();
    };

    prefetch(0, 0);
    for (int ch = 0; ch < DMODEL / 64; ch++) {
        if (ch + 1 < DMODEL / 64) { prefetch(ch + 1, (ch + 1) & 1); CP_WAIT1(); }
        else                      { CP_WAIT0(); }
        __syncthreads();

        const uint32_t base = sb + (ch & 1) * STAGE_SZ;
#pragma unroll
        for (int ks = 0; ks < 4; ks++) {
            uint32_t ah[2][4], al[2][4];
#pragma unroll
            for (int mi = 0; mi < 2; mi++) {
                const int row = a_row + mi * 16;
                const uint32_t co = (uint32_t)(((ks * 2 + a_chalf) ^ rm8) << 4);
                ldsm_x4(ah[mi][0], ah[mi][1], ah[mi][2], ah[mi][3],
                        base + OFF_AH + row * 128 + co);
                ldsm_x4(al[mi][0], al[mi][1], al[mi][2], al[mi][3],
                        base + OFF_AL + row * 128 + co);
            }
#pragma unroll
            for (int np = 0; np < 4; np++) {
                const int nrow = b_nloc + np * 16;
                const uint32_t co = (uint32_t)(((ks * 2 + b_chalf) ^ rm8) << 4);
                uint32_t bh0, bh1, bh2, bh3, bl0, bl1, bl2, bl3;
                ldsm_x4(bh0, bh1, bh2, bh3, base + OFF_BH + nrow * 128 + co);
                ldsm_x4(bl0, bl1, bl2, bl3, base + OFF_BL + nrow * 128 + co);
#pragma unroll
                for (int mi = 0; mi < 2; mi++) {
                    mma_bf16(acc[mi][np * 2],     ah[mi], bh0, bh1);
                    mma_bf16(acc[mi][np * 2],     ah[mi], bl0, bl1);
                    mma_bf16(acc[mi][np * 2],     al[mi], bh0, bh1);
                    mma_bf16(acc[mi][np * 2 + 1], ah[mi], bh2, bh3);
                    mma_bf16(acc[mi][np * 2 + 1], ah[mi], bl2, bl3);
                    mma_bf16(acc[mi][np * 2 + 1], al[mi], bh2, bh3);
                }
            }
        }
        __syncthreads();
    }

    const int erow = bm + warp_m * 32 + (lane >> 2);
    const int ecol = bn + warp_n * 64 + (lane & 3) * 2;
#pragma unroll
    for (int mi = 0; mi < 2; mi++) {
#pragma unroll
        for (int nj = 0; nj < 8; nj++) {
            const int gc = ecol + nj * 8;
            const float b0 = bias[gc], b1 = bias[gc + 1];
#pragma unroll
            for (int half = 0; half < 2; half++) {
                const int gr = erow + mi * 16 + half * 8;
                const float v0 = (acc[mi][nj][half * 2]     + b0) * scale;
                const float v1 = (acc[mi][nj][half * 2 + 1] + b1) * scale;
                if (!qkv_mode) {
                    *(float2*)(outf + (size_t)gr * DMODEL + gc) = make_float2(v0, v1);
                } else {
                    const int b = gr >> 11, s = gr & 2047;
                    const int h = gc >> 6,  d = gc & 63;
                    const size_t oi = (((size_t)b * HNUM + h) * SEQ + s) * DK + d;
                    __nv_bfloat16 h0 = __float2bfloat16(v0), h1 = __float2bfloat16(v1);
                    __nv_bfloat16 e0 = __float2bfloat16(v0 - __bfloat162float(h0));
                    __nv_bfloat16 e1 = __float2bfloat16(v1 - __bfloat162float(h1));
                    *(__nv_bfloat162*)(outh + oi) = __nv_bfloat162(h0, h1);
                    *(__nv_bfloat162*)(outl + oi) = __nv_bfloat162(e0, e1);
                }
            }
        }
    }
}

// ---------------------------------------------------------------------------
// MMA flash attention, cp.async double-buffered KV pipeline.
// ---------------------------------------------------------------------------
#define AT_KH 0u
#define AT_KL 16384u
#define AT_VH 32768u
#define AT_VL 49152u
#define ATTN_SMEM 131072

__global__ void __launch_bounds__(256, 1) attn_mma_kernel(
    const __nv_bfloat16* __restrict__ Qh, const __nv_bfloat16* __restrict__ Ql,
    const __nv_bfloat16* __restrict__ Kh, const __nv_bfloat16* __restrict__ Kl,
    const __nv_bfloat16* __restrict__ Vh, const __nv_bfloat16* __restrict__ Vl,
    const int* __restrict__ mask,
    __nv_bfloat16* __restrict__ Oh, __nv_bfloat16* __restrict__ Ol)
{
    extern __shared__ __align__(16) char smem[];
    __shared__ int msk[2][128];
    const uint32_t sb = smem_to_u32(smem);
    const int tid = threadIdx.x, lane = tid & 31, wid = tid >> 5;
    const int bh = blockIdx.y, b = bh / HNUM, h = bh % HNUM;
    const int q0 = blockIdx.x * 128;
    const size_t hb = (size_t)bh * SEQ * DK;
    const int rm8 = lane & 7;

    // Stage Q tile in stage-0 K area, pull fragments
    for (int i = tid; i < 1024; i += 256) {
        const int r = i >> 3, c = i & 7;
        const uint32_t so = (uint32_t)(r * 128 + ((c ^ (r & 7)) << 4));
        const size_t g = hb + (size_t)(q0 + r) * DK + c * 8;
        *(uint4*)(smem + AT_KH + so) = *(const uint4*)(Qh + g);
        *(uint4*)(smem + AT_KL + so) = *(const uint4*)(Ql + g);
    }
    if (tid < 128) msk[0][tid] = mask[b * SEQ + tid];
    __syncthreads();

    const int arow = wid * 16 + (lane & 15);
    const int ach  = lane >> 4;
    uint32_t qfh[4][4], qfl[4][4];
#pragma unroll
    for (int ks = 0; ks < 4; ks++) {
        const uint32_t co = (uint32_t)(((ks * 2 + ach) ^ rm8) << 4);
        ldsm_x4(qfh[ks][0], qfh[ks][1], qfh[ks][2], qfh[ks][3],
                sb + AT_KH + arow * 128 + co);
        ldsm_x4(qfl[ks][0], qfl[ks][1], qfl[ks][2], qfl[ks][3],
                sb + AT_KL + arow * 128 + co);
    }
    __syncthreads();

    float oacc[8][4];
#pragma unroll
    for (int nj = 0; nj < 8; nj++)
#pragma unroll
        for (int c = 0; c < 4; c++) oacc[nj][c] = 0.0f;
    float mr0 = -1e30f, mr1 = -1e30f, lr0 = 0.0f, lr1 = 0.0f;

    const int knloc = (lane & 7) + ((lane >> 4) << 3);
    const int kch   = (lane >> 3) & 1;
    const int vrow_base = (lane & 7) + (((lane >> 3) & 1) << 3);
    const int vch   = lane >> 4;
    const int c0i   = 2 * (lane & 3);

    auto prefetch_kv = [&](int ch, int st) {
        const uint32_t base = sb + st * STAGE_SZ;
        const int j0 = ch * 128;
#pragma unroll
        for (int i = tid; i < 1024; i += 256) {
            const int r = i >> 3, c = i & 7;
            const uint32_t so = (uint32_t)(r * 128 + ((c ^ (r & 7)) << 4));
            const size_t g = hb + (size_t)(j0 + r) * DK + c * 8;
            cp16(base + AT_KH + so, Kh + g);
            cp16(base + AT_KL + so, Kl + g);
            cp16(base + AT_VH + so, Vh + g);
            cp16(base + AT_VL + so, Vl + g);
        }
        CP_COMMIT();
    };

    prefetch_kv(0, 0);
    for (int ch = 0; ch < SEQ / 128; ch++) {
        if (ch + 1 < SEQ / 128) {
            prefetch_kv(ch + 1, (ch + 1) & 1);
            if (tid < 128) msk[(ch + 1) & 1][tid] = mask[b * SEQ + (ch + 1) * 128 + tid];
            CP_WAIT1();
        } else {
            CP_WAIT0();
        }
        __syncthreads();

        const uint32_t base = sb + (ch & 1) * STAGE_SZ;
        const int* mk = msk[ch & 1];

        float sacc[16][4];
#pragma unroll
        for (int nj = 0; nj < 16; nj++)
#pragma unroll
            for (int c = 0; c < 4; c++) sacc[nj][c] = 0.0f;

#pragma unroll
        for (int ks = 0; ks < 4; ks++) {
            const uint32_t co = (uint32_t)(((ks * 2 + kch) ^ rm8) << 4);
#pragma unroll
            for (int np = 0; np < 8; np++) {
                const int nrow = np * 16 + knloc;
                uint32_t h0, h1, h2, h3, l0, l1, l2, l3;
                ldsm_x4(h0, h1, h2, h3, base + AT_KH + nrow * 128 + co);
                ldsm_x4(l0, l1, l2, l3, base + AT_KL + nrow * 128 + co);
                mma_bf16(sacc[np * 2],     qfh[ks], h0, h1);
                mma_bf16(sacc[np * 2],     qfh[ks], l0, l1);
                mma_bf16(sacc[np * 2],     qfl[ks], h0, h1);
                mma_bf16(sacc[np * 2 + 1], qfh[ks], h2, h3);
                mma_bf16(sacc[np * 2 + 1], qfh[ks], l2, l3);
                mma_bf16(sacc[np * 2 + 1], qfl[ks], h2, h3);
            }
        }

#pragma unroll
        for (int nj = 0; nj < 16; nj++) {
            if (mk[nj * 8 + c0i] == 0)     { sacc[nj][0] = -1e9f; sacc[nj][2] = -1e9f; }
            if (mk[nj * 8 + c0i + 1] == 0) { sacc[nj][1] = -1e9f; sacc[nj][3] = -1e9f; }
        }

        float m0 = -1e30f, m1 = -1e30f;
#pragma unroll
        for (int nj = 0; nj < 16; nj++) {
            m0 = fmaxf(m0, fmaxf(sacc[nj][0], sacc[nj][1]));
            m1 = fmaxf(m1, fmaxf(sacc[nj][2], sacc[nj][3]));
        }
        m0 = fmaxf(m0, __shfl_xor_sync(0xffffffffu, m0, 1));
        m0 = fmaxf(m0, __shfl_xor_sync(0xffffffffu, m0, 2));
        m1 = fmaxf(m1, __shfl_xor_sync(0xffffffffu, m1, 1));
        m1 = fmaxf(m1, __shfl_xor_sync(0xffffffffu, m1, 2));
        const float mn0 = fmaxf(mr0, m0), mn1 = fmaxf(mr1, m1);
        const float al0 = __expf(mr0 - mn0), al1 = __expf(mr1 - mn1);
        mr0 = mn0; mr1 = mn1;

        float rs0 = 0.0f, rs1 = 0.0f;
        uint32_t phi[16][2], plo[16][2];
#pragma unroll
        for (int nj = 0; nj < 16; nj++) {
            const float p0 = __expf(sacc[nj][0] - mn0);
            const float p1 = __expf(sacc[nj][1] - mn0);
            const float p2 = __expf(sacc[nj][2] - mn1);
            const float p3 = __expf(sacc[nj][3] - mn1);
            rs0 += p0 + p1; rs1 += p2 + p3;
            const float h0 = __bfloat162float(__float2bfloat16(p0));
            const float h1 = __bfloat162float(__float2bfloat16(p1));
            const float h2 = __bfloat162float(__float2bfloat16(p2));
            const float h3 = __bfloat162float(__float2bfloat16(p3));
            phi[nj][0] = pack_bf16(h0, h1);
            phi[nj][1] = pack_bf16(h2, h3);
            plo[nj][0] = pack_bf16(p0 - h0, p1 - h1);
            plo[nj][1] = pack_bf16(p2 - h2, p3 - h3);
        }
        rs0 += __shfl_xor_sync(0xffffffffu, rs0, 1);
        rs0 += __shfl_xor_sync(0xffffffffu, rs0, 2);
        rs1 += __shfl_xor_sync(0xffffffffu, rs1, 1);
        rs1 += __shfl_xor_sync(0xffffffffu, rs1, 2);
        lr0 = lr0 * al0 + rs0;
        lr1 = lr1 * al1 + rs1;

#pragma unroll
        for (int nj = 0; nj < 8; nj++) {
            oacc[nj][0] *= al0; oacc[nj][1] *= al0;
            oacc[nj][2] *= al1; oacc[nj][3] *= al1;
        }

#pragma unroll
        for (int kt = 0; kt < 8; kt++) {
            uint32_t pah[4] = { phi[2 * kt][0], phi[2 * kt][1],
                                phi[2 * kt + 1][0], phi[2 * kt + 1][1] };
            uint32_t pal[4] = { plo[2 * kt][0], plo[2 * kt][1],
                                plo[2 * kt + 1][0], plo[2 * kt + 1][1] };
            const int vrow = kt * 16 + vrow_base;
#pragma unroll
            for (int np = 0; np < 4; np++) {
                const uint32_t co = (uint32_t)(((np * 2 + vch) ^ rm8) << 4);
                uint32_t h0, h1, h2, h3, l0, l1, l2, l3;
                ldsm_x4_t(h0, h1, h2, h3, base + AT_VH + vrow * 128 + co);
                ldsm_x4_t(l0, l1, l2, l3, base + AT_VL + vrow * 128 + co);
                mma_bf16(oacc[np * 2],     pah, h0, h1);
                mma_bf16(oacc[np * 2],     pah, l0, l1);
                mma_bf16(oacc[np * 2],     pal, h0, h1);
                mma_bf16(oacc[np * 2 + 1], pah, h2, h3);
                mma_bf16(oacc[np * 2 + 1], pah, l2, l3);
                mma_bf16(oacc[np * 2 + 1], pal, h2, h3);
            }
        }
        __syncthreads();
    }

    const float inv0 = 1.0f / lr0, inv1 = 1.0f / lr1;
    const int s0 = q0 + wid * 16 + (lane >> 2);
#pragma unroll
    for (int nj = 0; nj < 8; nj++) {
        const int d = nj * 8 + c0i;
#pragma unroll
        for (int half = 0; half < 2; half++) {
            const int s = s0 + half * 8;
            const float v0 = oacc[nj][half * 2]     * (half ? inv1 : inv0);
            const float v1 = oacc[nj][half * 2 + 1] * (half ? inv1 : inv0);
            const size_t oi = (size_t)(b * SEQ + s) * DMODEL + h * DK + d;
            __nv_bfloat16 h0 = __float2bfloat16(v0), h1 = __float2bfloat16(v1);
            __nv_bfloat16 e0 = __float2bfloat16(v0 - __bfloat162float(h0));
            __nv_bfloat16 e1 = __float2bfloat16(v1 - __bfloat162float(h1));
            *(__nv_bfloat162*)(Oh + oi) = __nv_bfloat162(h0, h1);
            *(__nv_bfloat162*)(Ol + oi) = __nv_bfloat162(e0, e1);
        }
    }
}

// ---------------------------------------------------------------------------
// Launch
// ---------------------------------------------------------------------------
extern "C" void kernel_launch(void* const* d_in, const int* in_sizes, int n_in,
                              void* d_out, int out_size)
{
    const float* query = (const float*)d_in[0];
    const float* key   = (const float*)d_in[1];
    const float* value = (const float*)d_in[2];
    const int*   mask  = (const int*)  d_in[3];
    const float* Wq    = (const float*)d_in[4];
    const float* bq    = (const float*)d_in[5];
    const float* Wk    = (const float*)d_in[6];
    const float* bk    = (const float*)d_in[7];
    const float* Wv    = (const float*)d_in[8];
    const float* bv    = (const float*)d_in[9];
    const float* Wo    = (const float*)d_in[10];
    const float* bo    = (const float*)d_in[11];

    __nv_bfloat16 *qh, *ql, *kh, *kl, *vh, *vl, *ah, *al, *wh, *wl, *oh, *ol;
    cudaGetSymbolAddress((void**)&qh, g_qh);
    cudaGetSymbolAddress((void**)&ql, g_ql);
    cudaGetSymbolAddress((void**)&kh, g_kh);
    cudaGetSymbolAddress((void**)&kl, g_kl);
    cudaGetSymbolAddress((void**)&vh, g_vh);
    cudaGetSymbolAddress((void**)&vl, g_vl);
    cudaGetSymbolAddress((void**)&ah, g_ah);
    cudaGetSymbolAddress((void**)&al, g_al);
    cudaGetSymbolAddress((void**)&wh, g_wh);
    cudaGetSymbolAddress((void**)&wl, g_wl);
    cudaGetSymbolAddress((void**)&oh, g_oh);
    cudaGetSymbolAddress((void**)&ol, g_ol);

    cudaFuncSetAttribute(tc_gemm_kernel,
                         cudaFuncAttributeMaxDynamicSharedMemorySize, GEMM_SMEM);
    cudaFuncSetAttribute(attn_mma_kernel,
                         cudaFuncAttributeMaxDynamicSharedMemorySize, ATTN_SMEM);

    const int a4 = NA_ / 4, w4 = NW_ / 4;

    // Split activations (z=3) and weights (z=4)
    cvt_split_kernel<<<dim3((a4 + 255) / 256, 3), 256>>>(
        query, key, value, nullptr,
        ah, ah + NA_, ah + 2 * NA_, nullptr,
        al, al + NA_, al + 2 * NA_, nullptr, a4);
    cvt_split_kernel<<<dim3((w4 + 255) / 256, 4), 256>>>(
        Wq, Wk, Wv, Wo,
        wh, wh + NW_, wh + 2 * NW_, wh + 3 * NW_,
        wl, wl + NW_, wl + 2 * NW_, wl + 3 * NW_, w4);

    // Fused Q/K/V projections (z selects)
    tc_gemm_kernel<<<dim3(DMODEL / 128, MTOT / 128, 3), 256, GEMM_SMEM>>>(
        ah, al, wh, wl, bq, bk, bv, nullptr,
        qh, ql, kh, kl, vh, vl, 1);

    attn_mma_kernel<<<dim3(SEQ / 128, BATCH * HNUM), 256, ATTN_SMEM>>>(
        qh, ql, kh, kl, vh, vl, mask, oh, ol);

    // Output projection
    tc_gemm_kernel<<<dim3(DMODEL / 128, MTOT / 128, 1), 256, GEMM_SMEM>>>(
        oh, ol, wh + 3 * NW_, wl + 3 * NW_, bo, nullptr, nullptr, (float*)d_out,
        nullptr, nullptr, nullptr, nullptr, nullptr, nullptr, 0);
}

// round 7
// speedup vs baseline: 4.5880x; 1.0343x over previous
#include <cuda_runtime.h>
#include <cuda_bf16.h>
#include <cstdint>
#include <math.h>

#define HNUM   12
#define DMODEL 768
#define BATCH  2
#define SEQ    2048
#define DK     64
#define MTOT   (BATCH * SEQ)          // 4096
#define NA_ (MTOT * DMODEL)           // 3145728
#define NW_ (DMODEL * DMODEL)         // 589824

// ---------------------------------------------------------------------------
// Scratch (allocation-free): everything bf16 hi/lo
// ---------------------------------------------------------------------------
__device__ __nv_bfloat16 g_qh[BATCH * HNUM * SEQ * DK];
__device__ __nv_bfloat16 g_ql[BATCH * HNUM * SEQ * DK];
__device__ __nv_bfloat16 g_kh[BATCH * HNUM * SEQ * DK];
__device__ __nv_bfloat16 g_kl[BATCH * HNUM * SEQ * DK];
__device__ __nv_bfloat16 g_vh[BATCH * HNUM * SEQ * DK];
__device__ __nv_bfloat16 g_vl[BATCH * HNUM * SEQ * DK];

__device__ __nv_bfloat16 g_ah[3 * NA_];
__device__ __nv_bfloat16 g_al[3 * NA_];
__device__ __nv_bfloat16 g_wh[4 * NW_];
__device__ __nv_bfloat16 g_wl[4 * NW_];
__device__ __nv_bfloat16 g_oh[NA_];
__device__ __nv_bfloat16 g_ol[NA_];

// ---------------------------------------------------------------------------
// Helpers
// ---------------------------------------------------------------------------
__device__ __forceinline__ uint32_t smem_to_u32(const void* p) {
    uint32_t a;
    asm("{ .reg .u64 t; cvta.to.shared.u64 t, %1; cvt.u32.u64 %0, t; }"
        : "=r"(a) : "l"(p));
    return a;
}
__device__ __forceinline__ void cp16(uint32_t s, const void* g) {
    asm volatile("cp.async.cg.shared.global [%0], [%1], 16;" :: "r"(s), "l"(g));
}
#define CP_COMMIT() asm volatile("cp.async.commit_group;" ::: "memory")
#define CP_WAIT1()  asm volatile("cp.async.wait_group 1;" ::: "memory")
#define CP_WAIT0()  asm volatile("cp.async.wait_group 0;" ::: "memory")

__device__ __forceinline__ void ldsm_x4(uint32_t& r0, uint32_t& r1,
                                        uint32_t& r2, uint32_t& r3, uint32_t addr) {
    asm volatile("ldmatrix.sync.aligned.m8n8.x4.shared.b16 {%0,%1,%2,%3}, [%4];"
                 : "=r"(r0), "=r"(r1), "=r"(r2), "=r"(r3) : "r"(addr));
}
__device__ __forceinline__ void ldsm_x4_t(uint32_t& r0, uint32_t& r1,
                                          uint32_t& r2, uint32_t& r3, uint32_t addr) {
    asm volatile("ldmatrix.sync.aligned.m8n8.x4.trans.shared.b16 {%0,%1,%2,%3}, [%4];"
                 : "=r"(r0), "=r"(r1), "=r"(r2), "=r"(r3) : "r"(addr));
}
__device__ __forceinline__ void mma_bf16(float* c, const uint32_t* a,
                                         uint32_t b0, uint32_t b1) {
    asm volatile("mma.sync.aligned.m16n8k16.row.col.f32.bf16.bf16.f32 "
                 "{%0,%1,%2,%3}, {%4,%5,%6,%7}, {%8,%9}, {%0,%1,%2,%3};"
                 : "+f"(c[0]), "+f"(c[1]), "+f"(c[2]), "+f"(c[3])
                 : "r"(a[0]), "r"(a[1]), "r"(a[2]), "r"(a[3]), "r"(b0), "r"(b1));
}
__device__ __forceinline__ uint32_t pack_bf16(float x, float y) {
    __nv_bfloat162 t = __floats2bfloat162_rn(x, y);
    return *(uint32_t*)&t;
}
__device__ __forceinline__ float ex2f(float x) {
    float y;
    asm("ex2.approx.ftz.f32 %0, %1;" : "=f"(y) : "f"(x));
    return y;
}

// ---------------------------------------------------------------------------
// Fused fp32 -> bf16 hi/lo split; blockIdx.y selects tensor
// ---------------------------------------------------------------------------
__global__ void __launch_bounds__(256) cvt_split_kernel(
    const float* x0, const float* x1, const float* x2, const float* x3,
    __nv_bfloat16* h0p, __nv_bfloat16* h1p, __nv_bfloat16* h2p, __nv_bfloat16* h3p,
    __nv_bfloat16* l0p, __nv_bfloat16* l1p, __nv_bfloat16* l2p, __nv_bfloat16* l3p,
    int n4)
{
    const int z = blockIdx.y;
    const float* x = (z == 0) ? x0 : (z == 1) ? x1 : (z == 2) ? x2 : x3;
    __nv_bfloat16* hi = (z == 0) ? h0p : (z == 1) ? h1p : (z == 2) ? h2p : h3p;
    __nv_bfloat16* lo = (z == 0) ? l0p : (z == 1) ? l1p : (z == 2) ? l2p : l3p;
    int i = blockIdx.x * 256 + threadIdx.x;
    if (i >= n4) return;
    float4 v = ((const float4*)x)[i];
    __nv_bfloat16 h0 = __float2bfloat16(v.x), h1 = __float2bfloat16(v.y);
    __nv_bfloat16 h2 = __float2bfloat16(v.z), h3 = __float2bfloat16(v.w);
    __nv_bfloat16 l0 = __float2bfloat16(v.x - __bfloat162float(h0));
    __nv_bfloat16 l1 = __float2bfloat16(v.y - __bfloat162float(h1));
    __nv_bfloat16 l2 = __float2bfloat16(v.z - __bfloat162float(h2));
    __nv_bfloat16 l3 = __float2bfloat16(v.w - __bfloat162float(h3));
    ((__nv_bfloat162*)hi)[2 * i]     = __nv_bfloat162(h0, h1);
    ((__nv_bfloat162*)hi)[2 * i + 1] = __nv_bfloat162(h2, h3);
    ((__nv_bfloat162*)lo)[2 * i]     = __nv_bfloat162(l0, l1);
    ((__nv_bfloat162*)lo)[2 * i + 1] = __nv_bfloat162(l2, l3);
}

// ---------------------------------------------------------------------------
// HMMA GEMM (bf16x3), cp.async double-buffered.
// CTA tile 128x256, 8 warps as 2(M)x4(N), warp tile 64x64, K-chunk 64.
// qkv_mode=1: blockIdx.z selects (A,W,bias,out); bf16 hi/lo [B,H,S,64] output.
// qkv_mode=0: fp32 row-major output.
// ---------------------------------------------------------------------------
#define OFF_AH 0u
#define OFF_AL 16384u
#define OFF_BH 32768u
#define OFF_BL 65536u
#define STAGE_SZ 98304u
#define GEMM_SMEM 196608

__global__ void __launch_bounds__(256, 1) tc_gemm_kernel(
    const __nv_bfloat16* Abase_h, const __nv_bfloat16* Abase_l,
    const __nv_bfloat16* Wbase_h, const __nv_bfloat16* Wbase_l,
    const float* bias0, const float* bias1, const float* bias2,
    float* outf,
    __nv_bfloat16* o0h, __nv_bfloat16* o0l,
    __nv_bfloat16* o1h, __nv_bfloat16* o1l,
    __nv_bfloat16* o2h, __nv_bfloat16* o2l,
    float scale0, int qkv_mode)
{
    extern __shared__ __align__(16) char smem[];
    const uint32_t sb = smem_to_u32(smem);
    const int tid  = threadIdx.x;
    const int lane = tid & 31;
    const int wid  = tid >> 5;
    const int wm   = wid & 1;      // 2 warps over M: 64 rows each
    const int wn   = wid >> 1;     // 4 warps over N: 64 cols each
    const int bm = blockIdx.y * 128;
    const int bn = blockIdx.x * 256;
    const int z  = blockIdx.z;

    const __nv_bfloat16* Ah = Abase_h + (size_t)z * NA_;
    const __nv_bfloat16* Al = Abase_l + (size_t)z * NA_;
    const __nv_bfloat16* Bh = Wbase_h + (size_t)z * NW_;
    const __nv_bfloat16* Bl = Wbase_l + (size_t)z * NW_;
    const float* bias = (z == 0) ? bias0 : (z == 1) ? bias1 : bias2;
    const float scale = (z == 0) ? scale0 : 1.0f;
    __nv_bfloat16* outh = (z == 0) ? o0h : (z == 1) ? o1h : o2h;
    __nv_bfloat16* outl = (z == 0) ? o0l : (z == 1) ? o1l : o2l;

    float acc[4][8][4];
#pragma unroll
    for (int mi = 0; mi < 4; mi++)
#pragma unroll
        for (int nj = 0; nj < 8; nj++)
#pragma unroll
            for (int c = 0; c < 4; c++) acc[mi][nj][c] = 0.0f;

    const int a_row   = wm * 64 + (lane & 15);          // + mi*16
    const int a_chalf = lane >> 4;
    const int b_nloc  = wn * 64 + (lane & 7) + ((lane >> 4) << 3);  // + np*16
    const int b_chalf = (lane >> 3) & 1;
    const int rm8     = lane & 7;

    auto prefetch = [&](int ch, int st) {
        const uint32_t base = sb + st * STAGE_SZ;
        const int k0 = ch * 64;
#pragma unroll
        for (int i = tid; i < 1024; i += 256) {   // A tiles: 128 rows
            const int r = i >> 3, c = i & 7;
            const uint32_t so = (uint32_t)(r * 128 + ((c ^ (r & 7)) << 4));
            const size_t ga = (size_t)(bm + r) * DMODEL + k0 + c * 8;
            cp16(base + OFF_AH + so, Ah + ga);
            cp16(base + OFF_AL + so, Al + ga);
        }
#pragma unroll
        for (int i = tid; i < 2048; i += 256) {   // B tiles: 256 rows
            const int r = i >> 3, c = i & 7;
            const uint32_t so = (uint32_t)(r * 128 + ((c ^ (r & 7)) << 4));
            const size_t gb = (size_t)(bn + r) * DMODEL + k0 + c * 8;
            cp16(base + OFF_BH + so, Bh + gb);
            cp16(base + OFF_BL + so, Bl + gb);
        }
        CP_COMMIT();
    };

    prefetch(0, 0);
    for (int ch = 0; ch < DMODEL / 64; ch++) {
        if (ch + 1 < DMODEL / 64) { prefetch(ch + 1, (ch + 1) & 1); CP_WAIT1(); }
        else                      { CP_WAIT0(); }
        __syncthreads();

        const uint32_t base = sb + (ch & 1) * STAGE_SZ;
#pragma unroll
        for (int ks = 0; ks < 4; ks++) {
            uint32_t ahf[4][4], alf[4][4];
            const uint32_t aco = (uint32_t)(((ks * 2 + a_chalf) ^ rm8) << 4);
#pragma unroll
            for (int mi = 0; mi < 4; mi++) {
                const int row = a_row + mi * 16;
                ldsm_x4(ahf[mi][0], ahf[mi][1], ahf[mi][2], ahf[mi][3],
                        base + OFF_AH + row * 128 + aco);
                ldsm_x4(alf[mi][0], alf[mi][1], alf[mi][2], alf[mi][3],
                        base + OFF_AL + row * 128 + aco);
            }
            const uint32_t bco = (uint32_t)(((ks * 2 + b_chalf) ^ rm8) << 4);
#pragma unroll
            for (int np = 0; np < 4; np++) {
                const int nrow = b_nloc + np * 16;
                uint32_t bh0, bh1, bh2, bh3, bl0, bl1, bl2, bl3;
                ldsm_x4(bh0, bh1, bh2, bh3, base + OFF_BH + nrow * 128 + bco);
                ldsm_x4(bl0, bl1, bl2, bl3, base + OFF_BL + nrow * 128 + bco);
#pragma unroll
                for (int mi = 0; mi < 4; mi++) {
                    mma_bf16(acc[mi][np * 2],     ahf[mi], bh0, bh1);
                    mma_bf16(acc[mi][np * 2],     ahf[mi], bl0, bl1);
                    mma_bf16(acc[mi][np * 2],     alf[mi], bh0, bh1);
                    mma_bf16(acc[mi][np * 2 + 1], ahf[mi], bh2, bh3);
                    mma_bf16(acc[mi][np * 2 + 1], ahf[mi], bl2, bl3);
                    mma_bf16(acc[mi][np * 2 + 1], alf[mi], bh2, bh3);
                }
            }
        }
        __syncthreads();
    }

    const int erow = bm + wm * 64 + (lane >> 2);
    const int ecol = bn + wn * 64 + (lane & 3) * 2;
#pragma unroll
    for (int mi = 0; mi < 4; mi++) {
#pragma unroll
        for (int nj = 0; nj < 8; nj++) {
            const int gc = ecol + nj * 8;
            const float b0 = bias[gc], b1 = bias[gc + 1];
#pragma unroll
            for (int half = 0; half < 2; half++) {
                const int gr = erow + mi * 16 + half * 8;
                const float v0 = (acc[mi][nj][half * 2]     + b0) * scale;
                const float v1 = (acc[mi][nj][half * 2 + 1] + b1) * scale;
                if (!qkv_mode) {
                    *(float2*)(outf + (size_t)gr * DMODEL + gc) = make_float2(v0, v1);
                } else {
                    const int b = gr >> 11, s = gr & 2047;
                    const int h = gc >> 6,  d = gc & 63;
                    const size_t oi = (((size_t)b * HNUM + h) * SEQ + s) * DK + d;
                    __nv_bfloat16 h0 = __float2bfloat16(v0), h1 = __float2bfloat16(v1);
                    __nv_bfloat16 e0 = __float2bfloat16(v0 - __bfloat162float(h0));
                    __nv_bfloat16 e1 = __float2bfloat16(v1 - __bfloat162float(h1));
                    *(__nv_bfloat162*)(outh + oi) = __nv_bfloat162(h0, h1);
                    *(__nv_bfloat162*)(outl + oi) = __nv_bfloat162(e0, e1);
                }
            }
        }
    }
}

// ---------------------------------------------------------------------------
// MMA flash attention, cp.async double-buffered KV pipeline.
// Q pre-scaled by 0.125*log2(e); softmax in base-2 (raw ex2).
// ---------------------------------------------------------------------------
#define AT_KH 0u
#define AT_KL 16384u
#define AT_VH 32768u
#define AT_VL 49152u
#define AT_STAGE 65536u
#define ATTN_SMEM 131072

__global__ void __launch_bounds__(256, 1) attn_mma_kernel(
    const __nv_bfloat16* __restrict__ Qh, const __nv_bfloat16* __restrict__ Ql,
    const __nv_bfloat16* __restrict__ Kh, const __nv_bfloat16* __restrict__ Kl,
    const __nv_bfloat16* __restrict__ Vh, const __nv_bfloat16* __restrict__ Vl,
    const int* __restrict__ mask,
    __nv_bfloat16* __restrict__ Oh, __nv_bfloat16* __restrict__ Ol)
{
    extern __shared__ __align__(16) char smem[];
    __shared__ int msk[2][128];
    const uint32_t sb = smem_to_u32(smem);
    const int tid = threadIdx.x, lane = tid & 31, wid = tid >> 5;
    const int bh = blockIdx.y, b = bh / HNUM, h = bh % HNUM;
    const int q0 = blockIdx.x * 128;
    const size_t hb = (size_t)bh * SEQ * DK;
    const int rm8 = lane & 7;

    for (int i = tid; i < 1024; i += 256) {
        const int r = i >> 3, c = i & 7;
        const uint32_t so = (uint32_t)(r * 128 + ((c ^ (r & 7)) << 4));
        const size_t g = hb + (size_t)(q0 + r) * DK + c * 8;
        *(uint4*)(smem + AT_KH + so) = *(const uint4*)(Qh + g);
        *(uint4*)(smem + AT_KL + so) = *(const uint4*)(Ql + g);
    }
    if (tid < 128) msk[0][tid] = mask[b * SEQ + tid];
    __syncthreads();

    const int arow = wid * 16 + (lane & 15);
    const int ach  = lane >> 4;
    uint32_t qfh[4][4], qfl[4][4];
#pragma unroll
    for (int ks = 0; ks < 4; ks++) {
        const uint32_t co = (uint32_t)(((ks * 2 + ach) ^ rm8) << 4);
        ldsm_x4(qfh[ks][0], qfh[ks][1], qfh[ks][2], qfh[ks][3],
                sb + AT_KH + arow * 128 + co);
        ldsm_x4(qfl[ks][0], qfl[ks][1], qfl[ks][2], qfl[ks][3],
                sb + AT_KL + arow * 128 + co);
    }
    __syncthreads();

    float oacc[8][4];
#pragma unroll
    for (int nj = 0; nj < 8; nj++)
#pragma unroll
        for (int c = 0; c < 4; c++) oacc[nj][c] = 0.0f;
    float mr0 = -1e30f, mr1 = -1e30f, lr0 = 0.0f, lr1 = 0.0f;

    const int knloc = (lane & 7) + ((lane >> 4) << 3);
    const int kch   = (lane >> 3) & 1;
    const int vrow_base = (lane & 7) + (((lane >> 3) & 1) << 3);
    const int vch   = lane >> 4;
    const int c0i   = 2 * (lane & 3);

    auto prefetch_kv = [&](int ch, int st) {
        const uint32_t base = sb + st * AT_STAGE;
        const int j0 = ch * 128;
#pragma unroll
        for (int i = tid; i < 1024; i += 256) {
            const int r = i >> 3, c = i & 7;
            const uint32_t so = (uint32_t)(r * 128 + ((c ^ (r & 7)) << 4));
            const size_t g = hb + (size_t)(j0 + r) * DK + c * 8;
            cp16(base + AT_KH + so, Kh + g);
            cp16(base + AT_KL + so, Kl + g);
            cp16(base + AT_VH + so, Vh + g);
            cp16(base + AT_VL + so, Vl + g);
        }
        CP_COMMIT();
    };

    prefetch_kv(0, 0);
    for (int ch = 0; ch < SEQ / 128; ch++) {
        if (ch + 1 < SEQ / 128) {
            prefetch_kv(ch + 1, (ch + 1) & 1);
            if (tid < 128) msk[(ch + 1) & 1][tid] = mask[b * SEQ + (ch + 1) * 128 + tid];
            CP_WAIT1();
        } else {
            CP_WAIT0();
        }
        __syncthreads();

        const uint32_t base = sb + (ch & 1) * AT_STAGE;
        const int* mk = msk[ch & 1];

        float sacc[16][4];
#pragma unroll
        for (int nj = 0; nj < 16; nj++)
#pragma unroll
            for (int c = 0; c < 4; c++) sacc[nj][c] = 0.0f;

#pragma unroll
        for (int ks = 0; ks < 4; ks++) {
            const uint32_t co = (uint32_t)(((ks * 2 + kch) ^ rm8) << 4);
#pragma unroll
            for (int np = 0; np < 8; np++) {
                const int nrow = np * 16 + knloc;
                uint32_t h0, h1, h2, h3, l0, l1, l2, l3;
                ldsm_x4(h0, h1, h2, h3, base + AT_KH + nrow * 128 + co);
                ldsm_x4(l0, l1, l2, l3, base + AT_KL + nrow * 128 + co);
                mma_bf16(sacc[np * 2],     qfh[ks], h0, h1);
                mma_bf16(sacc[np * 2],     qfh[ks], l0, l1);
                mma_bf16(sacc[np * 2],     qfl[ks], h0, h1);
                mma_bf16(sacc[np * 2 + 1], qfh[ks], h2, h3);
                mma_bf16(sacc[np * 2 + 1], qfh[ks], l2, l3);
                mma_bf16(sacc[np * 2 + 1], qfl[ks], h2, h3);
            }
        }

#pragma unroll
        for (int nj = 0; nj < 16; nj++) {
            if (mk[nj * 8 + c0i] == 0)     { sacc[nj][0] = -1e9f; sacc[nj][2] = -1e9f; }
            if (mk[nj * 8 + c0i + 1] == 0) { sacc[nj][1] = -1e9f; sacc[nj][3] = -1e9f; }
        }

        float m0 = -1e30f, m1 = -1e30f;
#pragma unroll
        for (int nj = 0; nj < 16; nj++) {
            m0 = fmaxf(m0, fmaxf(sacc[nj][0], sacc[nj][1]));
            m1 = fmaxf(m1, fmaxf(sacc[nj][2], sacc[nj][3]));
        }
        m0 = fmaxf(m0, __shfl_xor_sync(0xffffffffu, m0, 1));
        m0 = fmaxf(m0, __shfl_xor_sync(0xffffffffu, m0, 2));
        m1 = fmaxf(m1, __shfl_xor_sync(0xffffffffu, m1, 1));
        m1 = fmaxf(m1, __shfl_xor_sync(0xffffffffu, m1, 2));
        const float mn0 = fmaxf(mr0, m0), mn1 = fmaxf(mr1, m1);
        const float al0 = ex2f(mr0 - mn0), al1 = ex2f(mr1 - mn1);
        mr0 = mn0; mr1 = mn1;

        float rs0 = 0.0f, rs1 = 0.0f;
        uint32_t phi[16][2], plo[16][2];
#pragma unroll
        for (int nj = 0; nj < 16; nj++) {
            const float p0 = ex2f(sacc[nj][0] - mn0);
            const float p1 = ex2f(sacc[nj][1] - mn0);
            const float p2 = ex2f(sacc[nj][2] - mn1);
            const float p3 = ex2f(sacc[nj][3] - mn1);
            rs0 += p0 + p1; rs1 += p2 + p3;
            const float h0 = __bfloat162float(__float2bfloat16(p0));
            const float h1 = __bfloat162float(__float2bfloat16(p1));
            const float h2 = __bfloat162float(__float2bfloat16(p2));
            const float h3 = __bfloat162float(__float2bfloat16(p3));
            phi[nj][0] = pack_bf16(h0, h1);
            phi[nj][1] = pack_bf16(h2, h3);
            plo[nj][0] = pack_bf16(p0 - h0, p1 - h1);
            plo[nj][1] = pack_bf16(p2 - h2, p3 - h3);
        }
        rs0 += __shfl_xor_sync(0xffffffffu, rs0, 1);
        rs0 += __shfl_xor_sync(0xffffffffu, rs0, 2);
        rs1 += __shfl_xor_sync(0xffffffffu, rs1, 1);
        rs1 += __shfl_xor_sync(0xffffffffu, rs1, 2);
        lr0 = lr0 * al0 + rs0;
        lr1 = lr1 * al1 + rs1;

#pragma unroll
        for (int nj = 0; nj < 8; nj++) {
            oacc[nj][0] *= al0; oacc[nj][1] *= al0;
            oacc[nj][2] *= al1; oacc[nj][3] *= al1;
        }

#pragma unroll
        for (int kt = 0; kt < 8; kt++) {
            uint32_t pah[4] = { phi[2 * kt][0], phi[2 * kt][1],
                                phi[2 * kt + 1][0], phi[2 * kt + 1][1] };
            uint32_t pal[4] = { plo[2 * kt][0], plo[2 * kt][1],
                                plo[2 * kt + 1][0], plo[2 * kt + 1][1] };
            const int vrow = kt * 16 + vrow_base;
#pragma unroll
            for (int np = 0; np < 4; np++) {
                const uint32_t co = (uint32_t)(((np * 2 + vch) ^ rm8) << 4);
                uint32_t h0, h1, h2, h3, l0, l1, l2, l3;
                ldsm_x4_t(h0, h1, h2, h3, base + AT_VH + vrow * 128 + co);
                ldsm_x4_t(l0, l1, l2, l3, base + AT_VL + vrow * 128 + co);
                mma_bf16(oacc[np * 2],     pah, h0, h1);
                mma_bf16(oacc[np * 2],     pah, l0, l1);
                mma_bf16(oacc[np * 2],     pal, h0, h1);
                mma_bf16(oacc[np * 2 + 1], pah, h2, h3);
                mma_bf16(oacc[np * 2 + 1], pah, l2, l3);
                mma_bf16(oacc[np * 2 + 1], pal, h2, h3);
            }
        }
        __syncthreads();
    }

    const float inv0 = 1.0f / lr0, inv1 = 1.0f / lr1;
    const int s0 = q0 + wid * 16 + (lane >> 2);
#pragma unroll
    for (int nj = 0; nj < 8; nj++) {
        const int d = nj * 8 + c0i;
#pragma unroll
        for (int half = 0; half < 2; half++) {
            const int s = s0 + half * 8;
            const float v0 = oacc[nj][half * 2]     * (half ? inv1 : inv0);
            const float v1 = oacc[nj][half * 2 + 1] * (half ? inv1 : inv0);
            const size_t oi = (size_t)(b * SEQ + s) * DMODEL + h * DK + d;
            __nv_bfloat16 h0 = __float2bfloat16(v0), h1 = __float2bfloat16(v1);
            __nv_bfloat16 e0 = __float2bfloat16(v0 - __bfloat162float(h0));
            __nv_bfloat16 e1 = __float2bfloat16(v1 - __bfloat162float(h1));
            *(__nv_bfloat162*)(Oh + oi) = __nv_bfloat162(h0, h1);
            *(__nv_bfloat162*)(Ol + oi) = __nv_bfloat162(e0, e1);
        }
    }
}

// ---------------------------------------------------------------------------
// Launch
// ---------------------------------------------------------------------------
extern "C" void kernel_launch(void* const* d_in, const int* in_sizes, int n_in,
                              void* d_out, int out_size)
{
    const float* query = (const float*)d_in[0];
    const float* key   = (const float*)d_in[1];
    const float* value = (const float*)d_in[2];
    const int*   mask  = (const int*)  d_in[3];
    const float* Wq    = (const float*)d_in[4];
    const float* bq    = (const float*)d_in[5];
    const float* Wk    = (const float*)d_in[6];
    const float* bk    = (const float*)d_in[7];
    const float* Wv    = (const float*)d_in[8];
    const float* bv    = (const float*)d_in[9];
    const float* Wo    = (const float*)d_in[10];
    const float* bo    = (const float*)d_in[11];

    __nv_bfloat16 *qh, *ql, *kh, *kl, *vh, *vl, *ah, *al, *wh, *wl, *oh, *ol;
    cudaGetSymbolAddress((void**)&qh, g_qh);
    cudaGetSymbolAddress((void**)&ql, g_ql);
    cudaGetSymbolAddress((void**)&kh, g_kh);
    cudaGetSymbolAddress((void**)&kl, g_kl);
    cudaGetSymbolAddress((void**)&vh, g_vh);
    cudaGetSymbolAddress((void**)&vl, g_vl);
    cudaGetSymbolAddress((void**)&ah, g_ah);
    cudaGetSymbolAddress((void**)&al, g_al);
    cudaGetSymbolAddress((void**)&wh, g_wh);
    cudaGetSymbolAddress((void**)&wl, g_wl);
    cudaGetSymbolAddress((void**)&oh, g_oh);
    cudaGetSymbolAddress((void**)&ol, g_ol);

    cudaFuncSetAttribute(tc_gemm_kernel,
                         cudaFuncAttributeMaxDynamicSharedMemorySize, GEMM_SMEM);
    cudaFuncSetAttribute(attn_mma_kernel,
                         cudaFuncAttributeMaxDynamicSharedMemorySize, ATTN_SMEM);

    const int a4 = NA_ / 4, w4 = NW_ / 4;

    cvt_split_kernel<<<dim3((a4 + 255) / 256, 3), 256>>>(
        query, key, value, nullptr,
        ah, ah + NA_, ah + 2 * NA_, nullptr,
        al, al + NA_, al + 2 * NA_, nullptr, a4);
    cvt_split_kernel<<<dim3((w4 + 255) / 256, 4), 256>>>(
        Wq, Wk, Wv, Wo,
        wh, wh + NW_, wh + 2 * NW_, wh + 3 * NW_,
        wl, wl + NW_, wl + 2 * NW_, wl + 3 * NW_, w4);

    // Q scale folds 1/8 and log2(e) (softmax computed base-2 in attention)
    const float qscale = 0.125f * 1.4426950408889634f;

    tc_gemm_kernel<<<dim3(DMODEL / 256, MTOT / 128, 3), 256, GEMM_SMEM>>>(
        ah, al, wh, wl, bq, bk, bv, nullptr,
        qh, ql, kh, kl, vh, vl, qscale, 1);

    attn_mma_kernel<<<dim3(SEQ / 128, BATCH * HNUM), 256, ATTN_SMEM>>>(
        qh, ql, kh, kl, vh, vl, mask, oh, ol);

    tc_gemm_kernel<<<dim3(DMODEL / 256, MTOT / 128, 1), 256, GEMM_SMEM>>>(
        oh, ol, wh + 3 * NW_, wl + 3 * NW_, bo, nullptr, nullptr, (float*)d_out,
        nullptr, nullptr, nullptr, nullptr, nullptr, nullptr, 1.0f, 0);
}

// round 8
// speedup vs baseline: 4.7030x; 1.0251x over previous
#include <cuda_runtime.h>
#include <cuda_bf16.h>
#include <cstdint>
#include <math.h>

#define HNUM   12
#define DMODEL 768
#define BATCH  2
#define SEQ    2048
#define DK     64
#define MTOT   (BATCH * SEQ)          // 4096
#define NA_ (MTOT * DMODEL)           // 3145728
#define NW_ (DMODEL * DMODEL)         // 589824

// ---------------------------------------------------------------------------
// Scratch (allocation-free): everything bf16 hi/lo
// ---------------------------------------------------------------------------
__device__ __nv_bfloat16 g_qh[BATCH * HNUM * SEQ * DK];
__device__ __nv_bfloat16 g_ql[BATCH * HNUM * SEQ * DK];
__device__ __nv_bfloat16 g_kh[BATCH * HNUM * SEQ * DK];
__device__ __nv_bfloat16 g_kl[BATCH * HNUM * SEQ * DK];
__device__ __nv_bfloat16 g_vh[BATCH * HNUM * SEQ * DK];
__device__ __nv_bfloat16 g_vl[BATCH * HNUM * SEQ * DK];

__device__ __nv_bfloat16 g_ah[3 * NA_];
__device__ __nv_bfloat16 g_al[3 * NA_];
__device__ __nv_bfloat16 g_wh[4 * NW_];
__device__ __nv_bfloat16 g_wl[4 * NW_];
__device__ __nv_bfloat16 g_oh[NA_];
__device__ __nv_bfloat16 g_ol[NA_];

// ---------------------------------------------------------------------------
// Helpers
// ---------------------------------------------------------------------------
__device__ __forceinline__ uint32_t smem_to_u32(const void* p) {
    uint32_t a;
    asm("{ .reg .u64 t; cvta.to.shared.u64 t, %1; cvt.u32.u64 %0, t; }"
        : "=r"(a) : "l"(p));
    return a;
}
__device__ __forceinline__ void cp16(uint32_t s, const void* g) {
    asm volatile("cp.async.cg.shared.global [%0], [%1], 16;" :: "r"(s), "l"(g));
}
#define CP_COMMIT() asm volatile("cp.async.commit_group;" ::: "memory")
#define CP_WAIT1()  asm volatile("cp.async.wait_group 1;" ::: "memory")
#define CP_WAIT0()  asm volatile("cp.async.wait_group 0;" ::: "memory")

__device__ __forceinline__ void ldsm_x4(uint32_t& r0, uint32_t& r1,
                                        uint32_t& r2, uint32_t& r3, uint32_t addr) {
    asm volatile("ldmatrix.sync.aligned.m8n8.x4.shared.b16 {%0,%1,%2,%3}, [%4];"
                 : "=r"(r0), "=r"(r1), "=r"(r2), "=r"(r3) : "r"(addr));
}
__device__ __forceinline__ void ldsm_x4_t(uint32_t& r0, uint32_t& r1,
                                          uint32_t& r2, uint32_t& r3, uint32_t addr) {
    asm volatile("ldmatrix.sync.aligned.m8n8.x4.trans.shared.b16 {%0,%1,%2,%3}, [%4];"
                 : "=r"(r0), "=r"(r1), "=r"(r2), "=r"(r3) : "r"(addr));
}
__device__ __forceinline__ void mma_bf16(float* c, const uint32_t* a,
                                         uint32_t b0, uint32_t b1) {
    asm volatile("mma.sync.aligned.m16n8k16.row.col.f32.bf16.bf16.f32 "
                 "{%0,%1,%2,%3}, {%4,%5,%6,%7}, {%8,%9}, {%0,%1,%2,%3};"
                 : "+f"(c[0]), "+f"(c[1]), "+f"(c[2]), "+f"(c[3])
                 : "r"(a[0]), "r"(a[1]), "r"(a[2]), "r"(a[3]), "r"(b0), "r"(b1));
}
__device__ __forceinline__ uint32_t pack_bf16(float x, float y) {
    __nv_bfloat162 t = __floats2bfloat162_rn(x, y);
    return *(uint32_t*)&t;
}
// pack truncated-bf16 of two fp32: result = [hi16(a), hi16(b)]
__device__ __forceinline__ uint32_t prmt7632(uint32_t a, uint32_t b) {
    uint32_t r;
    asm("prmt.b32 %0, %1, %2, 0x7632;" : "=r"(r) : "r"(a), "r"(b));
    return r;
}
__device__ __forceinline__ float ex2f(float x) {
    float y;
    asm("ex2.approx.ftz.f32 %0, %1;" : "=f"(y) : "f"(x));
    return y;
}
// truncation hi/lo split of a pair -> (hi_packed, lo_packed)
__device__ __forceinline__ void split2(float v0, float v1,
                                       uint32_t& hp, uint32_t& lp) {
    const uint32_t b0 = __float_as_uint(v0), b1 = __float_as_uint(v1);
    hp = prmt7632(b0, b1);
    const float h0 = __uint_as_float(b0 & 0xffff0000u);
    const float h1 = __uint_as_float(b1 & 0xffff0000u);
    lp = pack_bf16(v0 - h0, v1 - h1);
}

// ---------------------------------------------------------------------------
// Fused fp32 -> bf16 hi/lo split; blockIdx.y selects tensor
// ---------------------------------------------------------------------------
__global__ void __launch_bounds__(256) cvt_split_kernel(
    const float* x0, const float* x1, const float* x2, const float* x3,
    __nv_bfloat16* h0p, __nv_bfloat16* h1p, __nv_bfloat16* h2p, __nv_bfloat16* h3p,
    __nv_bfloat16* l0p, __nv_bfloat16* l1p, __nv_bfloat16* l2p, __nv_bfloat16* l3p,
    int n4)
{
    const int z = blockIdx.y;
    const float* x = (z == 0) ? x0 : (z == 1) ? x1 : (z == 2) ? x2 : x3;
    __nv_bfloat16* hi = (z == 0) ? h0p : (z == 1) ? h1p : (z == 2) ? h2p : h3p;
    __nv_bfloat16* lo = (z == 0) ? l0p : (z == 1) ? l1p : (z == 2) ? l2p : l3p;
    int i = blockIdx.x * 256 + threadIdx.x;
    if (i >= n4) return;
    float4 v = ((const float4*)x)[i];
    uint32_t hp0, lp0, hp1, lp1;
    split2(v.x, v.y, hp0, lp0);
    split2(v.z, v.w, hp1, lp1);
    ((uint32_t*)hi)[2 * i]     = hp0;
    ((uint32_t*)hi)[2 * i + 1] = hp1;
    ((uint32_t*)lo)[2 * i]     = lp0;
    ((uint32_t*)lo)[2 * i + 1] = lp1;
}

// ---------------------------------------------------------------------------
// HMMA GEMM (bf16x3), cp.async double-buffered.
// CTA tile 128x256, 8 warps as 2(M)x4(N), warp tile 64x64, K-chunk 64.
// ---------------------------------------------------------------------------
#define OFF_AH 0u
#define OFF_AL 16384u
#define OFF_BH 32768u
#define OFF_BL 65536u
#define STAGE_SZ 98304u
#define GEMM_SMEM 196608

__global__ void __launch_bounds__(256, 1) tc_gemm_kernel(
    const __nv_bfloat16* Abase_h, const __nv_bfloat16* Abase_l,
    const __nv_bfloat16* Wbase_h, const __nv_bfloat16* Wbase_l,
    const float* bias0, const float* bias1, const float* bias2,
    float* outf,
    __nv_bfloat16* o0h, __nv_bfloat16* o0l,
    __nv_bfloat16* o1h, __nv_bfloat16* o1l,
    __nv_bfloat16* o2h, __nv_bfloat16* o2l,
    float scale0, int qkv_mode)
{
    extern __shared__ __align__(16) char smem[];
    const uint32_t sb = smem_to_u32(smem);
    const int tid  = threadIdx.x;
    const int lane = tid & 31;
    const int wid  = tid >> 5;
    const int wm   = wid & 1;
    const int wn   = wid >> 1;
    const int bm = blockIdx.y * 128;
    const int bn = blockIdx.x * 256;
    const int z  = blockIdx.z;

    const __nv_bfloat16* Ah = Abase_h + (size_t)z * NA_;
    const __nv_bfloat16* Al = Abase_l + (size_t)z * NA_;
    const __nv_bfloat16* Bh = Wbase_h + (size_t)z * NW_;
    const __nv_bfloat16* Bl = Wbase_l + (size_t)z * NW_;
    const float* bias = (z == 0) ? bias0 : (z == 1) ? bias1 : bias2;
    const float scale = (z == 0) ? scale0 : 1.0f;
    __nv_bfloat16* outh = (z == 0) ? o0h : (z == 1) ? o1h : o2h;
    __nv_bfloat16* outl = (z == 0) ? o0l : (z == 1) ? o1l : o2l;

    float acc[4][8][4];
#pragma unroll
    for (int mi = 0; mi < 4; mi++)
#pragma unroll
        for (int nj = 0; nj < 8; nj++)
#pragma unroll
            for (int c = 0; c < 4; c++) acc[mi][nj][c] = 0.0f;

    const int a_row   = wm * 64 + (lane & 15);
    const int a_chalf = lane >> 4;
    const int b_nloc  = wn * 64 + (lane & 7) + ((lane >> 4) << 3);
    const int b_chalf = (lane >> 3) & 1;
    const int rm8     = lane & 7;

    auto prefetch = [&](int ch, int st) {
        const uint32_t base = sb + st * STAGE_SZ;
        const int k0 = ch * 64;
#pragma unroll
        for (int i = tid; i < 1024; i += 256) {
            const int r = i >> 3, c = i & 7;
            const uint32_t so = (uint32_t)(r * 128 + ((c ^ (r & 7)) << 4));
            const size_t ga = (size_t)(bm + r) * DMODEL + k0 + c * 8;
            cp16(base + OFF_AH + so, Ah + ga);
            cp16(base + OFF_AL + so, Al + ga);
        }
#pragma unroll
        for (int i = tid; i < 2048; i += 256) {
            const int r = i >> 3, c = i & 7;
            const uint32_t so = (uint32_t)(r * 128 + ((c ^ (r & 7)) << 4));
            const size_t gb = (size_t)(bn + r) * DMODEL + k0 + c * 8;
            cp16(base + OFF_BH + so, Bh + gb);
            cp16(base + OFF_BL + so, Bl + gb);
        }
        CP_COMMIT();
    };

    prefetch(0, 0);
    for (int ch = 0; ch < DMODEL / 64; ch++) {
        if (ch + 1 < DMODEL / 64) { prefetch(ch + 1, (ch + 1) & 1); CP_WAIT1(); }
        else                      { CP_WAIT0(); }
        __syncthreads();

        const uint32_t base = sb + (ch & 1) * STAGE_SZ;
#pragma unroll
        for (int ks = 0; ks < 4; ks++) {
            uint32_t ahf[4][4], alf[4][4];
            const uint32_t aco = (uint32_t)(((ks * 2 + a_chalf) ^ rm8) << 4);
#pragma unroll
            for (int mi = 0; mi < 4; mi++) {
                const int row = a_row + mi * 16;
                ldsm_x4(ahf[mi][0], ahf[mi][1], ahf[mi][2], ahf[mi][3],
                        base + OFF_AH + row * 128 + aco);
                ldsm_x4(alf[mi][0], alf[mi][1], alf[mi][2], alf[mi][3],
                        base + OFF_AL + row * 128 + aco);
            }
            const uint32_t bco = (uint32_t)(((ks * 2 + b_chalf) ^ rm8) << 4);
#pragma unroll
            for (int np = 0; np < 4; np++) {
                const int nrow = b_nloc + np * 16;
                uint32_t bh0, bh1, bh2, bh3, bl0, bl1, bl2, bl3;
                ldsm_x4(bh0, bh1, bh2, bh3, base + OFF_BH + nrow * 128 + bco);
                ldsm_x4(bl0, bl1, bl2, bl3, base + OFF_BL + nrow * 128 + bco);
#pragma unroll
                for (int mi = 0; mi < 4; mi++) {
                    mma_bf16(acc[mi][np * 2],     ahf[mi], bh0, bh1);
                    mma_bf16(acc[mi][np * 2],     ahf[mi], bl0, bl1);
                    mma_bf16(acc[mi][np * 2],     alf[mi], bh0, bh1);
                    mma_bf16(acc[mi][np * 2 + 1], ahf[mi], bh2, bh3);
                    mma_bf16(acc[mi][np * 2 + 1], ahf[mi], bl2, bl3);
                    mma_bf16(acc[mi][np * 2 + 1], alf[mi], bh2, bh3);
                }
            }
        }
        __syncthreads();
    }

    const int erow = bm + wm * 64 + (lane >> 2);
    const int ecol = bn + wn * 64 + (lane & 3) * 2;
#pragma unroll
    for (int mi = 0; mi < 4; mi++) {
#pragma unroll
        for (int nj = 0; nj < 8; nj++) {
            const int gc = ecol + nj * 8;
            const float b0 = bias[gc], b1 = bias[gc + 1];
#pragma unroll
            for (int half = 0; half < 2; half++) {
                const int gr = erow + mi * 16 + half * 8;
                const float v0 = (acc[mi][nj][half * 2]     + b0) * scale;
                const float v1 = (acc[mi][nj][half * 2 + 1] + b1) * scale;
                if (!qkv_mode) {
                    *(float2*)(outf + (size_t)gr * DMODEL + gc) = make_float2(v0, v1);
                } else {
                    const int b = gr >> 11, s = gr & 2047;
                    const int h = gc >> 6,  d = gc & 63;
                    const size_t oi = (((size_t)b * HNUM + h) * SEQ + s) * DK + d;
                    uint32_t hp, lp;
                    split2(v0, v1, hp, lp);
                    *(uint32_t*)(outh + oi) = hp;
                    *(uint32_t*)(outl + oi) = lp;
                }
            }
        }
    }
}

// ---------------------------------------------------------------------------
// MMA flash attention, software-pipelined halves:
//   QK(A); QK(B); softmax(A); PV(A); softmax(B); PV(B)
// so softmax ALU overlaps queued tensor work.
// ---------------------------------------------------------------------------
#define AT_KH 0u
#define AT_KL 16384u
#define AT_VH 32768u
#define AT_VL 49152u
#define AT_STAGE 65536u
#define ATTN_SMEM 131072

__device__ __forceinline__ void qk_half(
    uint32_t base, int np_base,
    const uint32_t (&qfh)[4][4], const uint32_t (&qfl)[4][4],
    float (&sacc)[8][4], int knloc, int kch, int rm8)
{
#pragma unroll
    for (int nj = 0; nj < 8; nj++)
#pragma unroll
        for (int c = 0; c < 4; c++) sacc[nj][c] = 0.0f;
#pragma unroll
    for (int ks = 0; ks < 4; ks++) {
        const uint32_t co = (uint32_t)(((ks * 2 + kch) ^ rm8) << 4);
#pragma unroll
        for (int np = 0; np < 4; np++) {
            const int nrow = (np_base + np) * 16 + knloc;
            uint32_t h0, h1, h2, h3, l0, l1, l2, l3;
            ldsm_x4(h0, h1, h2, h3, base + AT_KH + nrow * 128 + co);
            ldsm_x4(l0, l1, l2, l3, base + AT_KL + nrow * 128 + co);
            mma_bf16(sacc[np * 2],     qfh[ks], h0, h1);
            mma_bf16(sacc[np * 2],     qfh[ks], l0, l1);
            mma_bf16(sacc[np * 2],     qfl[ks], h0, h1);
            mma_bf16(sacc[np * 2 + 1], qfh[ks], h2, h3);
            mma_bf16(sacc[np * 2 + 1], qfh[ks], l2, l3);
            mma_bf16(sacc[np * 2 + 1], qfl[ks], h2, h3);
        }
    }
}

__device__ __forceinline__ void softmax_half(
    float (&sacc)[8][4], const int* mk, int half, int c0i,
    float& mr0, float& mr1, float& lr0, float& lr1,
    float (&oacc)[8][4], uint32_t (&phi)[8][2], uint32_t (&plo)[8][2])
{
#pragma unroll
    for (int nj = 0; nj < 8; nj++) {
        const int ki = half * 64 + nj * 8 + c0i;
        if (mk[ki] == 0)     { sacc[nj][0] = -1e9f; sacc[nj][2] = -1e9f; }
        if (mk[ki + 1] == 0) { sacc[nj][1] = -1e9f; sacc[nj][3] = -1e9f; }
    }
    float m0 = -1e30f, m1 = -1e30f;
#pragma unroll
    for (int nj = 0; nj < 8; nj++) {
        m0 = fmaxf(m0, fmaxf(sacc[nj][0], sacc[nj][1]));
        m1 = fmaxf(m1, fmaxf(sacc[nj][2], sacc[nj][3]));
    }
    m0 = fmaxf(m0, __shfl_xor_sync(0xffffffffu, m0, 1));
    m0 = fmaxf(m0, __shfl_xor_sync(0xffffffffu, m0, 2));
    m1 = fmaxf(m1, __shfl_xor_sync(0xffffffffu, m1, 1));
    m1 = fmaxf(m1, __shfl_xor_sync(0xffffffffu, m1, 2));
    const float mn0 = fmaxf(mr0, m0), mn1 = fmaxf(mr1, m1);
    const float al0 = ex2f(mr0 - mn0), al1 = ex2f(mr1 - mn1);
    mr0 = mn0; mr1 = mn1;

    float rs0 = 0.0f, rs1 = 0.0f;
#pragma unroll
    for (int nj = 0; nj < 8; nj++) {
        const float p0 = ex2f(sacc[nj][0] - mn0);
        const float p1 = ex2f(sacc[nj][1] - mn0);
        const float p2 = ex2f(sacc[nj][2] - mn1);
        const float p3 = ex2f(sacc[nj][3] - mn1);
        rs0 += p0 + p1; rs1 += p2 + p3;
        split2(p0, p1, phi[nj][0], plo[nj][0]);
        split2(p2, p3, phi[nj][1], plo[nj][1]);
    }
    rs0 += __shfl_xor_sync(0xffffffffu, rs0, 1);
    rs0 += __shfl_xor_sync(0xffffffffu, rs0, 2);
    rs1 += __shfl_xor_sync(0xffffffffu, rs1, 1);
    rs1 += __shfl_xor_sync(0xffffffffu, rs1, 2);
    lr0 = lr0 * al0 + rs0;
    lr1 = lr1 * al1 + rs1;
#pragma unroll
    for (int nj = 0; nj < 8; nj++) {
        oacc[nj][0] *= al0; oacc[nj][1] *= al0;
        oacc[nj][2] *= al1; oacc[nj][3] *= al1;
    }
}

__device__ __forceinline__ void pv_half(
    uint32_t base, int half,
    const uint32_t (&phi)[8][2], const uint32_t (&plo)[8][2],
    float (&oacc)[8][4], int vrow_base, int vch, int rm8)
{
#pragma unroll
    for (int kt = 0; kt < 4; kt++) {
        uint32_t pah[4] = { phi[2 * kt][0], phi[2 * kt][1],
                            phi[2 * kt + 1][0], phi[2 * kt + 1][1] };
        uint32_t pal[4] = { plo[2 * kt][0], plo[2 * kt][1],
                            plo[2 * kt + 1][0], plo[2 * kt + 1][1] };
        const int vrow = (half * 4 + kt) * 16 + vrow_base;
#pragma unroll
        for (int np = 0; np < 4; np++) {
            const uint32_t co = (uint32_t)(((np * 2 + vch) ^ rm8) << 4);
            uint32_t h0, h1, h2, h3, l0, l1, l2, l3;
            ldsm_x4_t(h0, h1, h2, h3, base + AT_VH + vrow * 128 + co);
            ldsm_x4_t(l0, l1, l2, l3, base + AT_VL + vrow * 128 + co);
            mma_bf16(oacc[np * 2],     pah, h0, h1);
            mma_bf16(oacc[np * 2],     pah, l0, l1);
            mma_bf16(oacc[np * 2],     pal, h0, h1);
            mma_bf16(oacc[np * 2 + 1], pah, h2, h3);
            mma_bf16(oacc[np * 2 + 1], pah, l2, l3);
            mma_bf16(oacc[np * 2 + 1], pal, h2, h3);
        }
    }
}

__global__ void __launch_bounds__(256, 1) attn_mma_kernel(
    const __nv_bfloat16* __restrict__ Qh, const __nv_bfloat16* __restrict__ Ql,
    const __nv_bfloat16* __restrict__ Kh, const __nv_bfloat16* __restrict__ Kl,
    const __nv_bfloat16* __restrict__ Vh, const __nv_bfloat16* __restrict__ Vl,
    const int* __restrict__ mask,
    __nv_bfloat16* __restrict__ Oh, __nv_bfloat16* __restrict__ Ol)
{
    extern __shared__ __align__(16) char smem[];
    __shared__ int msk[2][128];
    const uint32_t sb = smem_to_u32(smem);
    const int tid = threadIdx.x, lane = tid & 31, wid = tid >> 5;
    const int bh = blockIdx.y, b = bh / HNUM, h = bh % HNUM;
    const int q0 = blockIdx.x * 128;
    const size_t hb = (size_t)bh * SEQ * DK;
    const int rm8 = lane & 7;

    for (int i = tid; i < 1024; i += 256) {
        const int r = i >> 3, c = i & 7;
        const uint32_t so = (uint32_t)(r * 128 + ((c ^ (r & 7)) << 4));
        const size_t g = hb + (size_t)(q0 + r) * DK + c * 8;
        *(uint4*)(smem + AT_KH + so) = *(const uint4*)(Qh + g);
        *(uint4*)(smem + AT_KL + so) = *(const uint4*)(Ql + g);
    }
    if (tid < 128) msk[0][tid] = mask[b * SEQ + tid];
    __syncthreads();

    const int arow = wid * 16 + (lane & 15);
    const int ach  = lane >> 4;
    uint32_t qfh[4][4], qfl[4][4];
#pragma unroll
    for (int ks = 0; ks < 4; ks++) {
        const uint32_t co = (uint32_t)(((ks * 2 + ach) ^ rm8) << 4);
        ldsm_x4(qfh[ks][0], qfh[ks][1], qfh[ks][2], qfh[ks][3],
                sb + AT_KH + arow * 128 + co);
        ldsm_x4(qfl[ks][0], qfl[ks][1], qfl[ks][2], qfl[ks][3],
                sb + AT_KL + arow * 128 + co);
    }
    __syncthreads();

    float oacc[8][4];
#pragma unroll
    for (int nj = 0; nj < 8; nj++)
#pragma unroll
        for (int c = 0; c < 4; c++) oacc[nj][c] = 0.0f;
    float mr0 = -1e30f, mr1 = -1e30f, lr0 = 0.0f, lr1 = 0.0f;

    const int knloc = (lane & 7) + ((lane >> 4) << 3);
    const int kch   = (lane >> 3) & 1;
    const int vrow_base = (lane & 7) + (((lane >> 3) & 1) << 3);
    const int vch   = lane >> 4;
    const int c0i   = 2 * (lane & 3);

    auto prefetch_kv = [&](int ch, int st) {
        const uint32_t base = sb + st * AT_STAGE;
        const int j0 = ch * 128;
#pragma unroll
        for (int i = tid; i < 1024; i += 256) {
            const int r = i >> 3, c = i & 7;
            const uint32_t so = (uint32_t)(r * 128 + ((c ^ (r & 7)) << 4));
            const size_t g = hb + (size_t)(j0 + r) * DK + c * 8;
            cp16(base + AT_KH + so, Kh + g);
            cp16(base + AT_KL + so, Kl + g);
            cp16(base + AT_VH + so, Vh + g);
            cp16(base + AT_VL + so, Vl + g);
        }
        CP_COMMIT();
    };

    prefetch_kv(0, 0);
    for (int ch = 0; ch < SEQ / 128; ch++) {
        if (ch + 1 < SEQ / 128) {
            prefetch_kv(ch + 1, (ch + 1) & 1);
            if (tid < 128) msk[(ch + 1) & 1][tid] = mask[b * SEQ + (ch + 1) * 128 + tid];
            CP_WAIT1();
        } else {
            CP_WAIT0();
        }
        __syncthreads();

        const uint32_t base = sb + (ch & 1) * AT_STAGE;
        const int* mk = msk[ch & 1];

        float saccA[8][4], saccB[8][4];
        qk_half(base, 0, qfh, qfl, saccA, knloc, kch, rm8);
        qk_half(base, 4, qfh, qfl, saccB, knloc, kch, rm8);

        uint32_t phiA[8][2], ploA[8][2];
        softmax_half(saccA, mk, 0, c0i, mr0, mr1, lr0, lr1, oacc, phiA, ploA);
        pv_half(base, 0, phiA, ploA, oacc, vrow_base, vch, rm8);

        uint32_t phiB[8][2], ploB[8][2];
        softmax_half(saccB, mk, 1, c0i, mr0, mr1, lr0, lr1, oacc, phiB, ploB);
        pv_half(base, 1, phiB, ploB, oacc, vrow_base, vch, rm8);

        __syncthreads();
    }

    const float inv0 = 1.0f / lr0, inv1 = 1.0f / lr1;
    const int s0 = q0 + wid * 16 + (lane >> 2);
#pragma unroll
    for (int nj = 0; nj < 8; nj++) {
        const int d = nj * 8 + c0i;
#pragma unroll
        for (int half = 0; half < 2; half++) {
            const int s = s0 + half * 8;
            const float v0 = oacc[nj][half * 2]     * (half ? inv1 : inv0);
            const float v1 = oacc[nj][half * 2 + 1] * (half ? inv1 : inv0);
            const size_t oi = (size_t)(b * SEQ + s) * DMODEL + h * DK + d;
            uint32_t hp, lp;
            split2(v0, v1, hp, lp);
            *(uint32_t*)(Oh + oi) = hp;
            *(uint32_t*)(Ol + oi) = lp;
        }
    }
}

// ---------------------------------------------------------------------------
// Launch
// ---------------------------------------------------------------------------
extern "C" void kernel_launch(void* const* d_in, const int* in_sizes, int n_in,
                              void* d_out, int out_size)
{
    const float* query = (const float*)d_in[0];
    const float* key   = (const float*)d_in[1];
    const float* value = (const float*)d_in[2];
    const int*   mask  = (const int*)  d_in[3];
    const float* Wq    = (const float*)d_in[4];
    const float* bq    = (const float*)d_in[5];
    const float* Wk    = (const float*)d_in[6];
    const float* bk    = (const float*)d_in[7];
    const float* Wv    = (const float*)d_in[8];
    const float* bv    = (const float*)d_in[9];
    const float* Wo    = (const float*)d_in[10];
    const float* bo    = (const float*)d_in[11];

    __nv_bfloat16 *qh, *ql, *kh, *kl, *vh, *vl, *ah, *al, *wh, *wl, *oh, *ol;
    cudaGetSymbolAddress((void**)&qh, g_qh);
    cudaGetSymbolAddress((void**)&ql, g_ql);
    cudaGetSymbolAddress((void**)&kh, g_kh);
    cudaGetSymbolAddress((void**)&kl, g_kl);
    cudaGetSymbolAddress((void**)&vh, g_vh);
    cudaGetSymbolAddress((void**)&vl, g_vl);
    cudaGetSymbolAddress((void**)&ah, g_ah);
    cudaGetSymbolAddress((void**)&al, g_al);
    cudaGetSymbolAddress((void**)&wh, g_wh);
    cudaGetSymbolAddress((void**)&wl, g_wl);
    cudaGetSymbolAddress((void**)&oh, g_oh);
    cudaGetSymbolAddress((void**)&ol, g_ol);

    cudaFuncSetAttribute(tc_gemm_kernel,
                         cudaFuncAttributeMaxDynamicSharedMemorySize, GEMM_SMEM);
    cudaFuncSetAttribute(attn_mma_kernel,
                         cudaFuncAttributeMaxDynamicSharedMemorySize, ATTN_SMEM);

    const int a4 = NA_ / 4, w4 = NW_ / 4;

    cvt_split_kernel<<<dim3((a4 + 255) / 256, 3), 256>>>(
        query, key, value, nullptr,
        ah, ah + NA_, ah + 2 * NA_, nullptr,
        al, al + NA_, al + 2 * NA_, nullptr, a4);
    cvt_split_kernel<<<dim3((w4 + 255) / 256, 4), 256>>>(
        Wq, Wk, Wv, Wo,
        wh, wh + NW_, wh + 2 * NW_, wh + 3 * NW_,
        wl, wl + NW_, wl + 2 * NW_, wl + 3 * NW_, w4);

    const float qscale = 0.125f * 1.4426950408889634f;

    tc_gemm_kernel<<<dim3(DMODEL / 256, MTOT / 128, 3), 256, GEMM_SMEM>>>(
        ah, al, wh, wl, bq, bk, bv, nullptr,
        qh, ql, kh, kl, vh, vl, qscale, 1);

    attn_mma_kernel<<<dim3(SEQ / 128, BATCH * HNUM), 256, ATTN_SMEM>>>(
        qh, ql, kh, kl, vh, vl, mask, oh, ol);

    tc_gemm_kernel<<<dim3(DMODEL / 256, MTOT / 128, 1), 256, GEMM_SMEM>>>(
        oh, ol, wh + 3 * NW_, wl + 3 * NW_, bo, nullptr, nullptr, (float*)d_out,
        nullptr, nullptr, nullptr, nullptr, nullptr, nullptr, 1.0f, 0);
}